// round 10
// baseline (speedup 1.0000x reference)
#include <cuda_runtime.h>
#include <cuda_fp16.h>
#include <math.h>

#define BB    4
#define NPN   4096          // points per batch
#define KNBR  32            // k
#define SL    64            // 2k slots
#define C1    64
#define C2    64
#define C3    128
#define NPTS  (BB*NPN)      // 16384
#define NCOLS (NPTS*SL)     // 1,048,576
#define NSTRIPE 32

// packed f32x2 FMA: acc = a*b + acc (two fp32 lanes per instruction)
#define FMA2(acc, a, b) \
    asm("fma.rn.f32x2 %0, %1, %2, %0;" : "+l"(acc) : "l"(a), "l"(b))

__device__ __forceinline__ void unpack2(unsigned long long v, float& lo, float& hi) {
    asm("mov.b64 {%0, %1}, %2;" : "=f"(lo), "=f"(hi) : "l"(v));
}

// ---------------- scratch (static device memory; no runtime allocation) ----
__device__ float  g_feats[(size_t)NCOLS*4];  // [point][slot][4] = resi.xyz, dist
__device__ float  g_y2  [(size_t)NCOLS*C2];  // [point][c][s] fp32
__device__ __half g_y3h [(size_t)NCOLS*C3];  // [point][c][s] fp16
__device__ __align__(16) float g_W2D[C1*C2*2];  // [i][c] duplicated {w,w}
__device__ __align__(16) float g_W3D[C2*C3*2];  // [i][c] duplicated {w,w}

__device__ double g_s1[C1], g_q1[C1];
__device__ double g_s2[NSTRIPE][C2], g_q2[NSTRIPE][C2];
__device__ double g_s3[NSTRIPE][C3], g_q3[NSTRIPE][C3];
__device__ float  g_a3[C3], g_d3[C3];

// ------------------------------------------------------------------- KNN
__device__ __forceinline__ unsigned int f2u_ordered(float f) {
    unsigned int u = __float_as_uint(f);
    return (u & 0x80000000u) ? ~u : (u | 0x80000000u);
}

__global__ __launch_bounds__(128) void knn_kernel(const float* __restrict__ p1,
                                                  const float* __restrict__ p2) {
    __shared__ unsigned int keys[NPN];
    __shared__ unsigned int hist[256];
    __shared__ unsigned int sel[KNBR];
    __shared__ unsigned int ties[40];
    __shared__ unsigned int s_cnt, s_tcnt, s_pref, s_kk;

    const int t   = threadIdx.x;
    const unsigned int bid = blockIdx.x;
    const int set = bid & 1;
    const int pq  = bid >> 1;
    const int b   = pq >> 12;
    const int n   = pq & (NPN-1);

    if (bid == 0) {   // fold stats zeroing into block 0
        for (int i = t; i < C1; i += 128) { g_s1[i] = 0.0; g_q1[i] = 0.0; }
        double* s2 = &g_s2[0][0]; double* q2 = &g_q2[0][0];
        for (int i = t; i < NSTRIPE*C2; i += 128) { s2[i] = 0.0; q2[i] = 0.0; }
        double* s3 = &g_s3[0][0]; double* q3 = &g_q3[0][0];
        for (int i = t; i < NSTRIPE*C3; i += 128) { s3[i] = 0.0; q3[i] = 0.0; }
    }

    const float* qb  = p1 + (size_t)b*3*NPN;
    const float* tgt = (set ? p2 : p1) + (size_t)b*3*NPN;

    const float qx = qb[n], qy = qb[NPN+n], qz = qb[2*NPN+n];
    const float qn = qx*qx + qy*qy + qz*qz;

    hist[t] = 0u; hist[t+128] = 0u;
    if (t == 0) { s_pref = 0u; s_kk = KNBR; s_cnt = 0u; s_tcnt = 0u; }
    __syncthreads();

    for (int j = t; j < NPN; j += 128) {
        float tx = tgt[j], ty = tgt[NPN+j], tz = tgt[2*NPN+j];
        float tn  = tx*tx + ty*ty + tz*tz;
        float dot = qx*tx + qy*ty + qz*tz;
        float d   = qn + tn - 2.0f*dot;
        unsigned int key = f2u_ordered(d);
        keys[j] = key;
        atomicAdd(&hist[key >> 24], 1u);
    }
    __syncthreads();

    #pragma unroll
    for (int pass = 0; pass < 4; pass++) {
        const int shift = 24 - pass*8;
        const unsigned int pref = s_pref;
        const unsigned int kk   = s_kk;
        if (t < 32) {
            const int base = t * 8;
            unsigned int vals[8];
            unsigned int s = 0;
            #pragma unroll
            for (int j = 0; j < 8; j++) { s += hist[base+j]; vals[j] = s; }
            unsigned int tot = s;
            #pragma unroll
            for (int off = 1; off < 32; off <<= 1) {
                unsigned int nb = __shfl_up_sync(0xffffffffu, tot, off);
                if (t >= off) tot += nb;
            }
            const unsigned int offset = tot - s;
            #pragma unroll
            for (int j = 0; j < 8; j++) hist[base+j] = vals[j] + offset;
        }
        __syncthreads();
        #pragma unroll
        for (int r = 0; r < 2; r++) {
            int bin = t + r*128;
            unsigned int cum  = hist[bin];
            unsigned int prev = bin ? hist[bin-1] : 0u;
            if (cum >= kk && prev < kk) {
                s_pref = pref | ((unsigned int)bin << shift);
                s_kk   = kk - prev;
            }
        }
        __syncthreads();
        if (pass < 3) {
            const unsigned int npref = s_pref;
            hist[t] = 0u; hist[t+128] = 0u;
            __syncthreads();
            const int nshift = shift - 8;
            const unsigned int nmask = 0xFFFFFFFFu << (nshift + 8);
            for (int j = t; j < NPN; j += 128) {
                unsigned int key = keys[j];
                if ((key & nmask) == npref)
                    atomicAdd(&hist[(key >> nshift) & 255u], 1u);
            }
            __syncthreads();
        }
    }

    const unsigned int T = s_pref;
    for (int j = t; j < NPN; j += 128) {
        unsigned int key = keys[j];
        if (key < T) {
            unsigned int pos = atomicAdd(&s_cnt, 1u);
            if (pos < KNBR) sel[pos] = (unsigned int)j;
        } else if (key == T) {
            unsigned int tp = atomicAdd(&s_tcnt, 1u);
            if (tp < 40u) ties[tp] = (unsigned int)j;
        }
    }
    __syncthreads();

    if (t == 0) {
        unsigned int cnt = s_cnt, kk = s_kk, tc = s_tcnt;
        if (cnt > KNBR) cnt = KNBR;
        if (kk > KNBR - cnt) kk = KNBR - cnt;
        if (tc <= 40u) {
            for (unsigned int m = 0; m < kk; m++) {
                unsigned int best = 0xFFFFFFFFu, bi = m;
                for (unsigned int r = m; r < tc; r++)
                    if (ties[r] < best) { best = ties[r]; bi = r; }
                ties[bi] = ties[m]; ties[m] = best;
                sel[cnt + m] = best;
            }
        } else {
            unsigned int filled = 0;
            for (int j = 0; j < NPN && filled < kk; j++)
                if (keys[j] == T) { sel[cnt + filled] = (unsigned int)j; filled++; }
        }
    }
    __syncthreads();

    if (t < KNBR) {
        int j = (int)sel[t];
        float tx = tgt[j], ty = tgt[NPN+j], tz = tgt[2*NPN+j];
        float rx = tx - qx, ry = ty - qy, rz = tz - qz;
        float dist = sqrtf(rx*rx + ry*ry + rz*rz);
        float4* out4 = (float4*)g_feats;
        out4[(size_t)pq*SL + set*KNBR + t] = make_float4(rx, ry, rz, dist);
    }
}

// --------- layer-1 BN statistics (+ duplicated weight tables in block 0) ---
__global__ __launch_bounds__(256) void stats1_kernel(const float* __restrict__ W1,
                                                     const float* __restrict__ b1,
                                                     const float* __restrict__ W2,
                                                     const float* __restrict__ W3) {
    __shared__ float w1s[C1*4];
    __shared__ float b1s[C1];
    __shared__ float ssum[C1], ssq[C1];
    const int t = threadIdx.x;

    if (blockIdx.x == 0) {
        for (int idx = t; idx < C2*C1; idx += 256) {
            int c = idx >> 6, i = idx & 63;
            float w = W2[idx];
            g_W2D[i*(C2*2) + c*2]     = w;
            g_W2D[i*(C2*2) + c*2 + 1] = w;
        }
        for (int idx = t; idx < C3*C2; idx += 256) {
            int c = idx >> 6, i = idx & 63;
            float w = W3[idx];
            g_W3D[i*(C3*2) + c*2]     = w;
            g_W3D[i*(C3*2) + c*2 + 1] = w;
        }
    }

    if (t < C1*4) w1s[t] = W1[t];
    if (t < C1)  { b1s[t] = b1[t]; ssum[t] = 0.f; ssq[t] = 0.f; }
    __syncthreads();

    const int c = t & 63, g = t >> 6;
    const int COLS_PER_BLOCK = NCOLS / 2048;
    const int col0 = blockIdx.x * COLS_PER_BLOCK;
    const float w0 = w1s[c*4+0], w1 = w1s[c*4+1], w2 = w1s[c*4+2], w3 = w1s[c*4+3];
    const float bc = b1s[c];
    float sum = 0.f, sq = 0.f;
    const float4* f4 = (const float4*)g_feats;
    for (int col = col0 + g; col < col0 + COLS_PER_BLOCK; col += 4) {
        float4 f = f4[col];
        float y = fmaf(w0, f.x, fmaf(w1, f.y, fmaf(w2, f.z, fmaf(w3, f.w, bc))));
        sum += y; sq = fmaf(y, y, sq);
    }
    atomicAdd(&ssum[c], sum);
    atomicAdd(&ssq[c],  sq);
    __syncthreads();
    if (t < C1) {
        atomicAdd(&g_s1[t], (double)ssum[t]);
        atomicAdd(&g_q1[t], (double)ssq[t]);
    }
}

// ------------------------------------ layer2: x2=relu(bn1(y1)), y2=W2 x2+b2
// 2 pts/block, 128 thr/pt: thread = 4ch x 8slots (16 acc64, low regs).
__global__ __launch_bounds__(256, 3) void layer2_kernel(const float* __restrict__ W1,
                                                        const float* __restrict__ b1,
                                                        const float* __restrict__ g1,
                                                        const float* __restrict__ be1,
                                                        const float* __restrict__ b2) {
    __shared__ __align__(16) float xs[2*4096];
    __shared__ __align__(16) float fsh[2*SL*4];
    __shared__ float w1s[C1*4];
    __shared__ float b1s[C1], a1s[C1], d1s[C1];
    __shared__ float ssum[C2], ssq[C2];

    const int t  = threadIdx.x;
    const int p0 = blockIdx.x * 2;

    w1s[t] = W1[t];
    if (t < 64) {
        b1s[t] = b1[t]; ssum[t] = 0.f; ssq[t] = 0.f;
        const double cnt = (double)NCOLS;
        double m = g_s1[t] / cnt;
        double v = g_q1[t] / cnt - m*m;
        if (v < 0.0) v = 0.0;
        double a = (double)g1[t] / sqrt(v + 1e-3);
        a1s[t] = (float)a;
        d1s[t] = (float)((double)be1[t] - a*m);
    }
    if (t < 128)
        ((float4*)fsh)[t] = ((const float4*)g_feats)[(size_t)p0*SL + t];
    __syncthreads();

    {   // x2 into smem: 8192 values, 32 per thread
        const float4* fsh4 = (const float4*)fsh;
        #pragma unroll 4
        for (int k = 0; k < 32; k++) {
            int idx = k*256 + t;
            int pt = idx >> 12;
            int i  = (idx >> 6) & 63;
            int s  = idx & 63;
            float4 f = fsh4[pt*SL + s];
            float y = fmaf(w1s[i*4+0], f.x, fmaf(w1s[i*4+1], f.y,
                      fmaf(w1s[i*4+2], f.z, fmaf(w1s[i*4+3], f.w, b1s[i]))));
            xs[pt*4096 + i*64 + s] = fmaxf(fmaf(a1s[i], y, d1s[i]), 0.f);
        }
    }
    __syncthreads();

    const int pt = t >> 7, r = t & 127;
    const int cq = r & 15, sg = r >> 4;         // 16 cquads x 8 slot-groups
    const float* xp = xs + pt*4096 + sg*8;
    const ulonglong2* wp = (const ulonglong2*)(g_W2D + cq*8);   // +i*(C2*2)

    unsigned long long acc[16];
    #pragma unroll
    for (int j = 0; j < 16; j++) acc[j] = 0ull;

    #pragma unroll 4
    for (int i = 0; i < C1; i++) {
        ulonglong2 wa = __ldg(wp + i*(C2/2));        // {w0,w0},{w1,w1}
        ulonglong2 wb = __ldg(wp + i*(C2/2) + 1);    // {w2,w2},{w3,w3}
        const ulonglong2* xr = (const ulonglong2*)(xp + i*64);
        ulonglong2 u0 = xr[0], u1 = xr[1];
        FMA2(acc[ 0], wa.x, u0.x); FMA2(acc[ 1], wa.x, u0.y);
        FMA2(acc[ 2], wa.x, u1.x); FMA2(acc[ 3], wa.x, u1.y);
        FMA2(acc[ 4], wa.y, u0.x); FMA2(acc[ 5], wa.y, u0.y);
        FMA2(acc[ 6], wa.y, u1.x); FMA2(acc[ 7], wa.y, u1.y);
        FMA2(acc[ 8], wb.x, u0.x); FMA2(acc[ 9], wb.x, u0.y);
        FMA2(acc[10], wb.x, u1.x); FMA2(acc[11], wb.x, u1.y);
        FMA2(acc[12], wb.y, u0.x); FMA2(acc[13], wb.y, u0.y);
        FMA2(acc[14], wb.y, u1.x); FMA2(acc[15], wb.y, u1.y);
    }

    float* ybase = g_y2 + (size_t)(p0 + pt)*(C2*SL) + sg*8;
    #pragma unroll
    for (int cc = 0; cc < 4; cc++) {
        const int c = cq*4 + cc;
        const float bc = b2[c];
        float v[8];
        #pragma unroll
        for (int sp = 0; sp < 4; sp++)
            unpack2(acc[cc*4 + sp], v[2*sp], v[2*sp+1]);
        float csum = 0.f, csq = 0.f;
        #pragma unroll
        for (int j = 0; j < 8; j++) {
            v[j] += bc; csum += v[j]; csq = fmaf(v[j], v[j], csq);
        }
        float4* o = (float4*)(ybase + c*64);
        o[0] = make_float4(v[0], v[1], v[2], v[3]);
        o[1] = make_float4(v[4], v[5], v[6], v[7]);
        atomicAdd(&ssum[c], csum);
        atomicAdd(&ssq[c],  csq);
    }
    __syncthreads();
    if (t < C2) {
        int r2 = blockIdx.x & (NSTRIPE-1);
        atomicAdd(&g_s2[r2][t], (double)ssum[t]);
        atomicAdd(&g_q2[r2][t], (double)ssq[t]);
    }
}

// ------------------------------------ layer3: x3=relu(bn2(y2)), y3=W3 x3+b3
// 1 pt/block, 256 thr: thread = 4ch x 8slots (16 acc64). Parallel BN2
// finalize in prologue; y3 stored fp16.
__global__ __launch_bounds__(256, 3) void layer3_kernel(const float* __restrict__ b3,
                                                        const float* __restrict__ g2,
                                                        const float* __restrict__ be2) {
    __shared__ __align__(16) float xs[4096];
    __shared__ float a2s[C2], d2s[C2];
    __shared__ float ssum[C3], ssq[C3];

    const int t = threadIdx.x;
    const int p = blockIdx.x;

    {   // parallel BN2 finalize: 4 groups x 8 stripes, reduce in xs alias
        double* red_s = (double*)xs;          // 256 doubles
        double* red_q = ((double*)xs) + 256;  // 256 doubles (4KB total)
        const int ch = t & 63, grp = t >> 6;
        double s = 0.0, q = 0.0;
        #pragma unroll
        for (int r = 0; r < 8; r++) {
            s += g_s2[grp*8 + r][ch];
            q += g_q2[grp*8 + r][ch];
        }
        red_s[t] = s; red_q[t] = q;
        __syncthreads();
        if (t < 64) {
            double ss = (red_s[t] + red_s[t+64]) + (red_s[t+128] + red_s[t+192]);
            double qq = (red_q[t] + red_q[t+64]) + (red_q[t+128] + red_q[t+192]);
            const double cnt = (double)NCOLS;
            double m = ss / cnt;
            double v = qq / cnt - m*m;
            if (v < 0.0) v = 0.0;
            double a = (double)g2[t] / sqrt(v + 1e-3);
            a2s[t] = (float)a;
            d2s[t] = (float)((double)be2[t] - a*m);
        }
        if (t < 128) { ssum[t] = 0.f; ssq[t] = 0.f; }
        __syncthreads();
    }

    {   // x3 into smem: 1024 float4, 4 per thread
        const float4* y2p = (const float4*)(g_y2 + (size_t)p*(C2*SL));
        float4* xs4 = (float4*)xs;
        #pragma unroll
        for (int k = 0; k < 4; k++) {
            int idx4 = k*256 + t;
            int i = idx4 >> 4;
            float a = a2s[i], d = d2s[i];
            float4 y = __ldg(&y2p[idx4]);
            float4 x;
            x.x = fmaxf(fmaf(a, y.x, d), 0.f);
            x.y = fmaxf(fmaf(a, y.y, d), 0.f);
            x.z = fmaxf(fmaf(a, y.z, d), 0.f);
            x.w = fmaxf(fmaf(a, y.w, d), 0.f);
            xs4[idx4] = x;
        }
    }
    __syncthreads();

    const int cq = t & 31, sg = t >> 5;         // 32 cquads x 8 slot-groups
    const float* xp = xs + sg*8;
    const ulonglong2* wp = (const ulonglong2*)(g_W3D + cq*8);   // +i*(C3*2)

    unsigned long long acc[16];
    #pragma unroll
    for (int j = 0; j < 16; j++) acc[j] = 0ull;

    #pragma unroll 4
    for (int i = 0; i < C2; i++) {
        ulonglong2 wa = __ldg(wp + i*(C3/2));
        ulonglong2 wb = __ldg(wp + i*(C3/2) + 1);
        const ulonglong2* xr = (const ulonglong2*)(xp + i*64);
        ulonglong2 u0 = xr[0], u1 = xr[1];
        FMA2(acc[ 0], wa.x, u0.x); FMA2(acc[ 1], wa.x, u0.y);
        FMA2(acc[ 2], wa.x, u1.x); FMA2(acc[ 3], wa.x, u1.y);
        FMA2(acc[ 4], wa.y, u0.x); FMA2(acc[ 5], wa.y, u0.y);
        FMA2(acc[ 6], wa.y, u1.x); FMA2(acc[ 7], wa.y, u1.y);
        FMA2(acc[ 8], wb.x, u0.x); FMA2(acc[ 9], wb.x, u0.y);
        FMA2(acc[10], wb.x, u1.x); FMA2(acc[11], wb.x, u1.y);
        FMA2(acc[12], wb.y, u0.x); FMA2(acc[13], wb.y, u0.y);
        FMA2(acc[14], wb.y, u1.x); FMA2(acc[15], wb.y, u1.y);
    }

    __half* ybase = g_y3h + (size_t)p*(C3*SL) + sg*8;
    #pragma unroll
    for (int cc = 0; cc < 4; cc++) {
        const int c = cq*4 + cc;
        const float bc = b3[c];
        float v[8];
        #pragma unroll
        for (int sp = 0; sp < 4; sp++)
            unpack2(acc[cc*4 + sp], v[2*sp], v[2*sp+1]);
        float csum = 0.f, csq = 0.f;
        #pragma unroll
        for (int j = 0; j < 8; j++) {
            v[j] += bc; csum += v[j]; csq = fmaf(v[j], v[j], csq);
        }
        __half2 h0 = __floats2half2_rn(v[0], v[1]);
        __half2 h1 = __floats2half2_rn(v[2], v[3]);
        __half2 h2 = __floats2half2_rn(v[4], v[5]);
        __half2 h3 = __floats2half2_rn(v[6], v[7]);
        uint4 pk;
        pk.x = *(unsigned int*)&h0; pk.y = *(unsigned int*)&h1;
        pk.z = *(unsigned int*)&h2; pk.w = *(unsigned int*)&h3;
        *(uint4*)(ybase + c*64) = pk;
        atomicAdd(&ssum[c], csum);
        atomicAdd(&ssq[c],  csq);
    }
    __syncthreads();
    if (t < C3) {
        int r = blockIdx.x & (NSTRIPE-1);
        atomicAdd(&g_s3[r][t], (double)ssum[t]);
        atomicAdd(&g_q3[r][t], (double)ssq[t]);
    }
}

__global__ void fin3_kernel(const float* __restrict__ g3, const float* __restrict__ be3) {
    int c = threadIdx.x;   // 128
    double s = 0.0, q = 0.0;
    for (int r = 0; r < NSTRIPE; r++) { s += g_s3[r][c]; q += g_q3[r][c]; }
    const double cnt = (double)NCOLS;
    double m = s / cnt;
    double v = q / cnt - m*m;
    if (v < 0.0) v = 0.0;
    double a = (double)g3[c] / sqrt(v + 1e-3);
    g_a3[c] = (float)a;
    g_d3[c] = (float)((double)be3[c] - a*m);
}

// --------------------------- max over channels, softmax over slots, fuse ---
__global__ __launch_bounds__(256) void fuse_kernel(const float* __restrict__ p1,
                                                   float* __restrict__ out) {
    __shared__ float pm[8][SL];
    __shared__ float sc[SL];
    __shared__ float ex[SL];
    __shared__ float rx[SL], ry[SL], rz[SL];

    const int t = threadIdx.x;
    const int p = blockIdx.x;
    const int s2 = t & 31, cg = t >> 5;    // thread: 2 slots x 16 channels

    const __half2* y3h2 = (const __half2*)(g_y3h + (size_t)p*(C3*SL));
    float m0 = -INFINITY, m1 = -INFINITY;
    #pragma unroll 4
    for (int ci = 0; ci < 16; ci++) {
        int c = cg*16 + ci;
        float a = g_a3[c], d = g_d3[c];
        float2 f = __half22float2(y3h2[c*32 + s2]);
        m0 = fmaxf(m0, fmaf(a, f.x, d));
        m1 = fmaxf(m1, fmaf(a, f.y, d));
    }
    pm[cg][2*s2]   = m0;
    pm[cg][2*s2+1] = m1;
    __syncthreads();

    if (t < SL) {
        float mm = pm[0][t];
        #pragma unroll
        for (int g = 1; g < 8; g++) mm = fmaxf(mm, pm[g][t]);
        sc[t] = fmaxf(mm, 0.f);     // relu then max == max then relu
    }
    __syncthreads();

    if (t < SL) {
        float mx = sc[0];
        #pragma unroll 8
        for (int i = 1; i < SL; i++) mx = fmaxf(mx, sc[i]);
        ex[t] = expf(sc[t] - mx);
    }
    __syncthreads();

    if (t < SL) {
        float ssum = 0.f;
        #pragma unroll 8
        for (int i = 0; i < SL; i++) ssum += ex[i];
        float w = ex[t] / ssum;
        float4 f = ((const float4*)g_feats)[(size_t)p*SL + t];
        rx[t] = w*f.x; ry[t] = w*f.y; rz[t] = w*f.z;
    }
    __syncthreads();

    for (int off = 32; off >= 1; off >>= 1) {
        if (t < off) { rx[t] += rx[t+off]; ry[t] += ry[t+off]; rz[t] += rz[t+off]; }
        __syncthreads();
    }

    if (t == 0) {
        const int b = p >> 12, n = p & (NPN-1);
        const float* q = p1 + (size_t)b*3*NPN;
        out[(size_t)b*3*NPN + n]          = q[n]        + rx[0];
        out[(size_t)b*3*NPN + NPN + n]    = q[NPN+n]    + ry[0];
        out[(size_t)b*3*NPN + 2*NPN + n]  = q[2*NPN+n]  + rz[0];
    }
}

// --------------------------------------------------------------------------
extern "C" void kernel_launch(void* const* d_in, const int* in_sizes, int n_in,
                              void* d_out, int out_size) {
    const float* points1 = (const float*)d_in[0];
    const float* points2 = (const float*)d_in[1];
    const float* W1  = (const float*)d_in[4];
    const float* b1  = (const float*)d_in[5];
    const float* g1  = (const float*)d_in[6];
    const float* be1 = (const float*)d_in[7];
    const float* W2  = (const float*)d_in[8];
    const float* b2  = (const float*)d_in[9];
    const float* g2  = (const float*)d_in[10];
    const float* be2 = (const float*)d_in[11];
    const float* W3  = (const float*)d_in[12];
    const float* b3  = (const float*)d_in[13];
    const float* g3  = (const float*)d_in[14];
    const float* be3 = (const float*)d_in[15];
    float* out = (float*)d_out;

    knn_kernel<<<BB*NPN*2, 128>>>(points1, points2);                 // 1
    stats1_kernel<<<2048, 256>>>(W1, b1, W2, W3);                    // 2
    layer2_kernel<<<NPTS/2, 256>>>(W1, b1, g1, be1, b2);             // 3
    layer3_kernel<<<NPTS, 256>>>(b3, g2, be2);                       // 4 -> ncu
    fin3_kernel<<<1, C3>>>(g3, be3);                                 // 5
    fuse_kernel<<<NPTS, 256>>>(points1, out);                        // 6
}

// round 11
// speedup vs baseline: 1.4538x; 1.4538x over previous
#include <cuda_runtime.h>
#include <cuda_fp16.h>
#include <math.h>

#define BB    4
#define NPN   4096          // points per batch
#define KNBR  32            // k
#define SL    64            // 2k slots
#define C1    64
#define C2    64
#define C3    128
#define NPTS  (BB*NPN)      // 16384
#define NCOLS (NPTS*SL)     // 1,048,576
#define NSTRIPE 32

// packed f32x2 FMA: acc = a*b + acc (two fp32 lanes per instruction)
#define FMA2(acc, a, b) \
    asm("fma.rn.f32x2 %0, %1, %2, %0;" : "+l"(acc) : "l"(a), "l"(b))

__device__ __forceinline__ unsigned long long pack_dup(float w) {
    unsigned long long r;
    asm("mov.b64 %0, {%1, %1};" : "=l"(r) : "f"(w));
    return r;
}
__device__ __forceinline__ void unpack2(unsigned long long v, float& lo, float& hi) {
    asm("mov.b64 {%0, %1}, %2;" : "=f"(lo), "=f"(hi) : "l"(v));
}

// ---------------- scratch (static device memory; no runtime allocation) ----
__device__ float  g_feats[(size_t)NCOLS*4];  // [point][slot][4] = resi.xyz, dist
__device__ float  g_y2  [(size_t)NCOLS*C2];  // [point][c][s] fp32
__device__ __half g_y3h [(size_t)NCOLS*C3];  // [point][c][s] fp16
__device__ float  g_W2T [C1*C2];             // [i][c]
__device__ float  g_W3T [C2*C3];             // [i][c]

__device__ double g_s1[C1], g_q1[C1];
__device__ double g_s2[NSTRIPE][C2], g_q2[NSTRIPE][C2];
__device__ double g_s3[NSTRIPE][C3], g_q3[NSTRIPE][C3];
__device__ float  g_a3[C3], g_d3[C3];

// ------------------------------------------------------------------- KNN
// radix select with candidate compaction: passes 1-3 + final selection only
// touch the shrinking candidate list (u16 indices), not all 4096 keys.
__device__ __forceinline__ unsigned int f2u_ordered(float f) {
    unsigned int u = __float_as_uint(f);
    return (u & 0x80000000u) ? ~u : (u | 0x80000000u);
}

__global__ __launch_bounds__(128) void knn_kernel(const float* __restrict__ p1,
                                                  const float* __restrict__ p2) {
    __shared__ unsigned int   keys[NPN];
    __shared__ unsigned short cand0[NPN];
    __shared__ unsigned short cand1[NPN];
    __shared__ unsigned int   hist[256];
    __shared__ unsigned int   sel[KNBR];
    __shared__ unsigned int   redbuf[128];
    __shared__ unsigned int   s_cnt, s_m, s_bin, s_kk, s_last;

    const int t   = threadIdx.x;
    const unsigned int bid = blockIdx.x;
    const int set = bid & 1;
    const int pq  = bid >> 1;
    const int b   = pq >> 12;
    const int n   = pq & (NPN-1);

    if (bid == 0) {   // fold stats zeroing into block 0
        for (int i = t; i < C1; i += 128) { g_s1[i] = 0.0; g_q1[i] = 0.0; }
        double* s2 = &g_s2[0][0]; double* q2 = &g_q2[0][0];
        for (int i = t; i < NSTRIPE*C2; i += 128) { s2[i] = 0.0; q2[i] = 0.0; }
        double* s3 = &g_s3[0][0]; double* q3 = &g_q3[0][0];
        for (int i = t; i < NSTRIPE*C3; i += 128) { s3[i] = 0.0; q3[i] = 0.0; }
    }

    const float* qb  = p1 + (size_t)b*3*NPN;
    const float* tgt = (set ? p2 : p1) + (size_t)b*3*NPN;

    const float qx = qb[n], qy = qb[NPN+n], qz = qb[2*NPN+n];
    const float qn = qx*qx + qy*qy + qz*qz;

    hist[t] = 0u; hist[t+128] = 0u;
    if (t == 0) { s_cnt = 0u; s_kk = KNBR; s_m = 0u; }
    __syncthreads();

    // phase A: distances -> keys, fused top-byte histogram
    for (int j = t; j < NPN; j += 128) {
        float tx = tgt[j], ty = tgt[NPN+j], tz = tgt[2*NPN+j];
        float tn  = tx*tx + ty*ty + tz*tz;
        float dot = qx*tx + qy*ty + qz*tz;
        float d   = qn + tn - 2.0f*dot;
        unsigned int key = f2u_ordered(d);
        keys[j] = key;
        atomicAdd(&hist[key >> 24], 1u);
    }
    __syncthreads();

    unsigned int mPrev = 0;
    #pragma unroll
    for (int pass = 0; pass < 4; pass++) {
        const int shift = 24 - pass*8;
        const unsigned int kk = s_kk;
        // warp 0: inclusive prefix over 256 bins
        if (t < 32) {
            const int base = t * 8;
            unsigned int vals[8];
            unsigned int s = 0;
            #pragma unroll
            for (int j = 0; j < 8; j++) { s += hist[base+j]; vals[j] = s; }
            unsigned int tot = s;
            #pragma unroll
            for (int off = 1; off < 32; off <<= 1) {
                unsigned int nb = __shfl_up_sync(0xffffffffu, tot, off);
                if (t >= off) tot += nb;
            }
            const unsigned int offset = tot - s;
            #pragma unroll
            for (int j = 0; j < 8; j++) hist[base+j] = vals[j] + offset;
        }
        __syncthreads();
        #pragma unroll
        for (int r = 0; r < 2; r++) {
            int bin = t + r*128;
            unsigned int cum  = hist[bin];
            unsigned int prev = bin ? hist[bin-1] : 0u;
            if (cum >= kk && prev < kk) {
                s_bin = (unsigned int)bin;
                s_kk  = kk - prev;
            }
        }
        __syncthreads();
        const unsigned int B   = s_bin;
        const unsigned int mIn = mPrev;
        hist[t] = 0u; hist[t+128] = 0u;
        if (t == 0) s_m = 0u;
        __syncthreads();

        const int nshift = shift - 8;
        if (pass == 0) {
            for (int j = t; j < NPN; j += 128) {
                unsigned int key  = keys[j];
                unsigned int byte = key >> 24;
                if (byte == B) {
                    unsigned int pos = atomicAdd(&s_m, 1u);
                    cand0[pos] = (unsigned short)j;
                    atomicAdd(&hist[(key >> 16) & 255u], 1u);
                } else if (byte < B) {
                    unsigned int pos = atomicAdd(&s_cnt, 1u);
                    if (pos < KNBR) sel[pos] = (unsigned int)j;
                }
            }
        } else {
            const unsigned short* src = (pass & 1) ? cand0 : cand1;
            unsigned short*       dst = (pass & 1) ? cand1 : cand0;
            for (unsigned int idx = t; idx < mIn; idx += 128) {
                unsigned int j    = src[idx];
                unsigned int key  = keys[j];
                unsigned int byte = (key >> shift) & 255u;
                if (byte == B) {
                    unsigned int pos = atomicAdd(&s_m, 1u);
                    dst[pos] = (unsigned short)j;
                    if (pass < 3) atomicAdd(&hist[(key >> nshift) & 255u], 1u);
                } else if (byte < B) {
                    unsigned int pos = atomicAdd(&s_cnt, 1u);
                    if (pos < KNBR) sel[pos] = (unsigned int)j;
                }
            }
        }
        __syncthreads();
        mPrev = s_m;
    }

    // ties: cand1 holds indices with key == T (count mPrev >= s_kk)
    {
        const unsigned int tcnt = mPrev;
        const unsigned int kk   = s_kk;
        unsigned int cnt = s_cnt; if (cnt > KNBR) cnt = KNBR;
        if (tcnt == kk) {
            if ((unsigned)t < tcnt) sel[cnt + t] = cand1[t];
            __syncthreads();
        } else {
            // choose kk smallest indices among ties (duplicate keys at T)
            unsigned int lastPlus = 0u;
            for (unsigned int m = 0; m < kk; m++) {
                unsigned int mymin = 0xFFFFFFFFu;
                for (unsigned int i = t; i < tcnt; i += 128) {
                    unsigned int j = cand1[i];
                    if (j >= lastPlus && j < mymin) mymin = j;
                }
                redbuf[t] = mymin;
                __syncthreads();
                for (int off = 64; off >= 1; off >>= 1) {
                    if (t < off) {
                        unsigned int o = redbuf[t+off];
                        if (o < redbuf[t]) redbuf[t] = o;
                    }
                    __syncthreads();
                }
                if (t == 0) { sel[cnt + m] = redbuf[0]; s_last = redbuf[0] + 1u; }
                __syncthreads();
                lastPlus = s_last;
            }
        }
    }
    __syncthreads();

    if (t < KNBR) {
        int j = (int)sel[t];
        float tx = tgt[j], ty = tgt[NPN+j], tz = tgt[2*NPN+j];
        float rx = tx - qx, ry = ty - qy, rz = tz - qz;
        float dist = sqrtf(rx*rx + ry*ry + rz*rz);
        float4* out4 = (float4*)g_feats;
        out4[(size_t)pq*SL + set*KNBR + t] = make_float4(rx, ry, rz, dist);
    }
}

// ----------------- layer-1 BN statistics (+ weight transposes in block 0) --
__global__ __launch_bounds__(256) void stats1_kernel(const float* __restrict__ W1,
                                                     const float* __restrict__ b1,
                                                     const float* __restrict__ W2,
                                                     const float* __restrict__ W3) {
    __shared__ float w1s[C1*4];
    __shared__ float b1s[C1];
    __shared__ float ssum[C1], ssq[C1];
    const int t = threadIdx.x;

    if (blockIdx.x == 0) {
        for (int idx = t; idx < C2*C1; idx += 256) {
            int c = idx >> 6, i = idx & 63;
            g_W2T[i*C2 + c] = W2[idx];
        }
        for (int idx = t; idx < C3*C2; idx += 256) {
            int c = idx >> 6, i = idx & 63;
            g_W3T[i*C3 + c] = W3[idx];
        }
    }

    if (t < C1*4) w1s[t] = W1[t];
    if (t < C1)  { b1s[t] = b1[t]; ssum[t] = 0.f; ssq[t] = 0.f; }
    __syncthreads();

    const int c = t & 63, g = t >> 6;
    const int COLS_PER_BLOCK = NCOLS / 2048;
    const int col0 = blockIdx.x * COLS_PER_BLOCK;
    const float w0 = w1s[c*4+0], w1 = w1s[c*4+1], w2 = w1s[c*4+2], w3 = w1s[c*4+3];
    const float bc = b1s[c];
    float sum = 0.f, sq = 0.f;
    const float4* f4 = (const float4*)g_feats;
    for (int col = col0 + g; col < col0 + COLS_PER_BLOCK; col += 4) {
        float4 f = f4[col];
        float y = fmaf(w0, f.x, fmaf(w1, f.y, fmaf(w2, f.z, fmaf(w3, f.w, bc))));
        sum += y; sq = fmaf(y, y, sq);
    }
    atomicAdd(&ssum[c], sum);
    atomicAdd(&ssq[c],  sq);
    __syncthreads();
    if (t < C1) {
        atomicAdd(&g_s1[t], (double)ssum[t]);
        atomicAdd(&g_q1[t], (double)ssq[t]);
    }
}

// ------------------------------------ layer2: x2=relu(bn1(y1)), y2=W2 x2+b2
// 4 pts/block (R7/R9 config). W2 rows via __ldg from g_W2T.
#define L2_XS    0
#define L2_FSH   (L2_XS + 4*4096)
#define L2_W1    (L2_FSH + 1024)
#define L2_B1    (L2_W1 + 256)
#define L2_A1    (L2_B1 + 64)
#define L2_D1    (L2_A1 + 64)
#define L2_SSUM  (L2_D1 + 64)
#define L2_SSQ   (L2_SSUM + 64)
#define L2_SMEM  ((L2_SSQ + 64) * sizeof(float))

__global__ __launch_bounds__(256, 2) void layer2_kernel(const float* __restrict__ W1,
                                                        const float* __restrict__ b1,
                                                        const float* __restrict__ g1,
                                                        const float* __restrict__ be1,
                                                        const float* __restrict__ b2) {
    extern __shared__ __align__(16) float sm[];
    float* xs   = sm + L2_XS;
    float* fsh  = sm + L2_FSH;
    float* w1s  = sm + L2_W1;
    float* b1s  = sm + L2_B1;
    float* a1s  = sm + L2_A1;
    float* d1s  = sm + L2_D1;
    float* ssum = sm + L2_SSUM;
    float* ssq  = sm + L2_SSQ;

    const int t  = threadIdx.x;
    const int p0 = blockIdx.x * 4;

    w1s[t] = W1[t];
    if (t < 64) {
        b1s[t] = b1[t]; ssum[t] = 0.f; ssq[t] = 0.f;
        const double cnt = (double)NCOLS;
        double m = g_s1[t] / cnt;
        double v = g_q1[t] / cnt - m*m;
        if (v < 0.0) v = 0.0;
        double a = (double)g1[t] / sqrt(v + 1e-3);
        a1s[t] = (float)a;
        d1s[t] = (float)((double)be1[t] - a*m);
    }
    ((float4*)fsh)[t] = ((const float4*)g_feats)[(size_t)p0*SL + t];
    __syncthreads();

    {
        const float4* fsh4 = (const float4*)fsh;
        #pragma unroll 4
        for (int k = 0; k < 64; k++) {
            int idx = k*256 + t;
            int pt = idx >> 12;
            int i  = (idx >> 6) & 63;
            int s  = idx & 63;
            float4 f = fsh4[pt*SL + s];
            float y = fmaf(w1s[i*4+0], f.x, fmaf(w1s[i*4+1], f.y,
                      fmaf(w1s[i*4+2], f.z, fmaf(w1s[i*4+3], f.w, b1s[i]))));
            xs[pt*4096 + i*64 + s] = fmaxf(fmaf(a1s[i], y, d1s[i]), 0.f);
        }
    }
    __syncthreads();

    const int pt = t >> 6, wt_tid = t & 63;
    const int cq = wt_tid & 15, sg = wt_tid >> 4;
    const float* xp = xs + pt*4096 + sg*16;
    const float4* wrow = ((const float4*)g_W2T) + cq;

    unsigned long long acc[32];
    #pragma unroll
    for (int j = 0; j < 32; j++) acc[j] = 0ull;

    float4 wv = __ldg(wrow);
    ulonglong2 u0, u1, u2, u3;
    { const ulonglong2* xr = (const ulonglong2*)xp;
      u0 = xr[0]; u1 = xr[1]; u2 = xr[2]; u3 = xr[3]; }

    #pragma unroll 2
    for (int i = 0; i < C1; i++) {
        const int inext = (i < C1-1) ? i+1 : i;
        float4 wn = __ldg(wrow + inext*16);
        const ulonglong2* xn = (const ulonglong2*)(xp + inext*64);
        ulonglong2 n0 = xn[0], n1 = xn[1], n2 = xn[2], n3 = xn[3];

        unsigned long long w0 = pack_dup(wv.x), w1 = pack_dup(wv.y);
        unsigned long long w2 = pack_dup(wv.z), w3 = pack_dup(wv.w);
        FMA2(acc[ 0], w0, u0.x); FMA2(acc[ 1], w0, u0.y);
        FMA2(acc[ 2], w0, u1.x); FMA2(acc[ 3], w0, u1.y);
        FMA2(acc[ 4], w0, u2.x); FMA2(acc[ 5], w0, u2.y);
        FMA2(acc[ 6], w0, u3.x); FMA2(acc[ 7], w0, u3.y);
        FMA2(acc[ 8], w1, u0.x); FMA2(acc[ 9], w1, u0.y);
        FMA2(acc[10], w1, u1.x); FMA2(acc[11], w1, u1.y);
        FMA2(acc[12], w1, u2.x); FMA2(acc[13], w1, u2.y);
        FMA2(acc[14], w1, u3.x); FMA2(acc[15], w1, u3.y);
        FMA2(acc[16], w2, u0.x); FMA2(acc[17], w2, u0.y);
        FMA2(acc[18], w2, u1.x); FMA2(acc[19], w2, u1.y);
        FMA2(acc[20], w2, u2.x); FMA2(acc[21], w2, u2.y);
        FMA2(acc[22], w2, u3.x); FMA2(acc[23], w2, u3.y);
        FMA2(acc[24], w3, u0.x); FMA2(acc[25], w3, u0.y);
        FMA2(acc[26], w3, u1.x); FMA2(acc[27], w3, u1.y);
        FMA2(acc[28], w3, u2.x); FMA2(acc[29], w3, u2.y);
        FMA2(acc[30], w3, u3.x); FMA2(acc[31], w3, u3.y);

        wv = wn; u0 = n0; u1 = n1; u2 = n2; u3 = n3;
    }

    float* ybase = g_y2 + (size_t)(p0 + pt)*(C2*SL) + sg*16;
    #pragma unroll
    for (int cc = 0; cc < 4; cc++) {
        const int c = cq*4 + cc;
        const float bc = b2[c];
        float v[16];
        #pragma unroll
        for (int sp = 0; sp < 8; sp++)
            unpack2(acc[cc*8 + sp], v[2*sp], v[2*sp+1]);
        float csum = 0.f, csq = 0.f;
        #pragma unroll
        for (int j = 0; j < 16; j++) {
            v[j] += bc; csum += v[j]; csq = fmaf(v[j], v[j], csq);
        }
        float4* o = (float4*)(ybase + c*64);
        o[0] = make_float4(v[0], v[1], v[2], v[3]);
        o[1] = make_float4(v[4], v[5], v[6], v[7]);
        o[2] = make_float4(v[8], v[9], v[10], v[11]);
        o[3] = make_float4(v[12], v[13], v[14], v[15]);
        atomicAdd(&ssum[c], csum);
        atomicAdd(&ssq[c],  csq);
    }
    __syncthreads();
    if (t < C2) {
        int r = blockIdx.x & (NSTRIPE-1);
        atomicAdd(&g_s2[r][t], (double)ssum[t]);
        atomicAdd(&g_q2[r][t], (double)ssq[t]);
    }
}

// ------------------------------------ layer3: x3=relu(bn2(y2)), y3=W3 x3+b3
// R9 config: 2 pts/block, 32 acc, pipelined, parallel BN2 finalize, fp16 y3.
__global__ __launch_bounds__(256, 2) void layer3_kernel(const float* __restrict__ b3,
                                                        const float* __restrict__ g2,
                                                        const float* __restrict__ be2) {
    __shared__ __align__(16) float xs[2*4096];
    __shared__ float a2s[C2], d2s[C2];
    __shared__ float ssum[C3], ssq[C3];

    const int t  = threadIdx.x;
    const int p0 = blockIdx.x * 2;

    {   // parallel BN2 finalize: 4 groups x 8 stripes, reduce in xs alias
        double* red_s = (double*)xs;
        double* red_q = ((double*)xs) + 256;
        const int ch = t & 63, grp = t >> 6;
        double s = 0.0, q = 0.0;
        #pragma unroll
        for (int r = 0; r < 8; r++) {
            s += g_s2[grp*8 + r][ch];
            q += g_q2[grp*8 + r][ch];
        }
        red_s[t] = s; red_q[t] = q;
        __syncthreads();
        if (t < 64) {
            double ss = (red_s[t] + red_s[t+64]) + (red_s[t+128] + red_s[t+192]);
            double qq = (red_q[t] + red_q[t+64]) + (red_q[t+128] + red_q[t+192]);
            const double cnt = (double)NCOLS;
            double m = ss / cnt;
            double v = qq / cnt - m*m;
            if (v < 0.0) v = 0.0;
            double a = (double)g2[t] / sqrt(v + 1e-3);
            a2s[t] = (float)a;
            d2s[t] = (float)((double)be2[t] - a*m);
        }
        if (t < 128) { ssum[t] = 0.f; ssq[t] = 0.f; }
        __syncthreads();
    }

    {   // x3 into smem from g_y2: 2048 float4, 8 per thread
        const float4* y2p = (const float4*)(g_y2 + (size_t)p0*(C2*SL));
        float4* xs4 = (float4*)xs;
        #pragma unroll
        for (int k = 0; k < 8; k++) {
            int idx4 = k*256 + t;
            int i = (idx4 >> 4) & 63;
            float a = a2s[i], d = d2s[i];
            float4 y = __ldg(&y2p[idx4]);
            float4 x;
            x.x = fmaxf(fmaf(a, y.x, d), 0.f);
            x.y = fmaxf(fmaf(a, y.y, d), 0.f);
            x.z = fmaxf(fmaf(a, y.z, d), 0.f);
            x.w = fmaxf(fmaf(a, y.w, d), 0.f);
            xs4[idx4] = x;
        }
    }
    __syncthreads();

    const int pt = t >> 7, wt_tid = t & 127;
    const int cq = wt_tid & 31, sg = wt_tid >> 5;
    const float* xp = xs + pt*4096 + sg*16;
    const float4* wrow = ((const float4*)g_W3T) + cq;

    unsigned long long acc[32];
    #pragma unroll
    for (int j = 0; j < 32; j++) acc[j] = 0ull;

    float4 wv = __ldg(wrow);
    ulonglong2 u0, u1, u2, u3;
    { const ulonglong2* xr = (const ulonglong2*)xp;
      u0 = xr[0]; u1 = xr[1]; u2 = xr[2]; u3 = xr[3]; }

    #pragma unroll 2
    for (int i = 0; i < C2; i++) {
        const int inext = (i < C2-1) ? i+1 : i;
        float4 wn = __ldg(wrow + inext*32);
        const ulonglong2* xn = (const ulonglong2*)(xp + inext*64);
        ulonglong2 n0 = xn[0], n1 = xn[1], n2 = xn[2], n3 = xn[3];

        unsigned long long w0 = pack_dup(wv.x), w1 = pack_dup(wv.y);
        unsigned long long w2 = pack_dup(wv.z), w3 = pack_dup(wv.w);
        FMA2(acc[ 0], w0, u0.x); FMA2(acc[ 1], w0, u0.y);
        FMA2(acc[ 2], w0, u1.x); FMA2(acc[ 3], w0, u1.y);
        FMA2(acc[ 4], w0, u2.x); FMA2(acc[ 5], w0, u2.y);
        FMA2(acc[ 6], w0, u3.x); FMA2(acc[ 7], w0, u3.y);
        FMA2(acc[ 8], w1, u0.x); FMA2(acc[ 9], w1, u0.y);
        FMA2(acc[10], w1, u1.x); FMA2(acc[11], w1, u1.y);
        FMA2(acc[12], w1, u2.x); FMA2(acc[13], w1, u2.y);
        FMA2(acc[14], w1, u3.x); FMA2(acc[15], w1, u3.y);
        FMA2(acc[16], w2, u0.x); FMA2(acc[17], w2, u0.y);
        FMA2(acc[18], w2, u1.x); FMA2(acc[19], w2, u1.y);
        FMA2(acc[20], w2, u2.x); FMA2(acc[21], w2, u2.y);
        FMA2(acc[22], w2, u3.x); FMA2(acc[23], w2, u3.y);
        FMA2(acc[24], w3, u0.x); FMA2(acc[25], w3, u0.y);
        FMA2(acc[26], w3, u1.x); FMA2(acc[27], w3, u1.y);
        FMA2(acc[28], w3, u2.x); FMA2(acc[29], w3, u2.y);
        FMA2(acc[30], w3, u3.x); FMA2(acc[31], w3, u3.y);

        wv = wn; u0 = n0; u1 = n1; u2 = n2; u3 = n3;
    }

    __half* ybase = g_y3h + (size_t)(p0 + pt)*(C3*SL) + sg*16;
    #pragma unroll
    for (int cc = 0; cc < 4; cc++) {
        const int c = cq*4 + cc;
        const float bc = b3[c];
        float v[16];
        #pragma unroll
        for (int sp = 0; sp < 8; sp++)
            unpack2(acc[cc*8 + sp], v[2*sp], v[2*sp+1]);
        float csum = 0.f, csq = 0.f;
        #pragma unroll
        for (int j = 0; j < 16; j++) {
            v[j] += bc; csum += v[j]; csq = fmaf(v[j], v[j], csq);
        }
        uint4 pk0, pk1;
        __half2 h;
        h = __floats2half2_rn(v[0],  v[1]);  pk0.x = *(unsigned int*)&h;
        h = __floats2half2_rn(v[2],  v[3]);  pk0.y = *(unsigned int*)&h;
        h = __floats2half2_rn(v[4],  v[5]);  pk0.z = *(unsigned int*)&h;
        h = __floats2half2_rn(v[6],  v[7]);  pk0.w = *(unsigned int*)&h;
        h = __floats2half2_rn(v[8],  v[9]);  pk1.x = *(unsigned int*)&h;
        h = __floats2half2_rn(v[10], v[11]); pk1.y = *(unsigned int*)&h;
        h = __floats2half2_rn(v[12], v[13]); pk1.z = *(unsigned int*)&h;
        h = __floats2half2_rn(v[14], v[15]); pk1.w = *(unsigned int*)&h;
        uint4* o = (uint4*)(ybase + c*64);
        o[0] = pk0; o[1] = pk1;
        atomicAdd(&ssum[c], csum);
        atomicAdd(&ssq[c],  csq);
    }
    __syncthreads();
    if (t < C3) {
        int r = blockIdx.x & (NSTRIPE-1);
        atomicAdd(&g_s3[r][t], (double)ssum[t]);
        atomicAdd(&g_q3[r][t], (double)ssq[t]);
    }
}

__global__ void fin3_kernel(const float* __restrict__ g3, const float* __restrict__ be3) {
    int c = threadIdx.x;   // 128
    double s = 0.0, q = 0.0;
    for (int r = 0; r < NSTRIPE; r++) { s += g_s3[r][c]; q += g_q3[r][c]; }
    const double cnt = (double)NCOLS;
    double m = s / cnt;
    double v = q / cnt - m*m;
    if (v < 0.0) v = 0.0;
    double a = (double)g3[c] / sqrt(v + 1e-3);
    g_a3[c] = (float)a;
    g_d3[c] = (float)((double)be3[c] - a*m);
}

// --------------------------- max over channels, softmax over slots, fuse ---
__global__ __launch_bounds__(256) void fuse_kernel(const float* __restrict__ p1,
                                                   float* __restrict__ out) {
    __shared__ float pm[8][SL];
    __shared__ float sc[SL];
    __shared__ float ex[SL];
    __shared__ float rx[SL], ry[SL], rz[SL];

    const int t = threadIdx.x;
    const int p = blockIdx.x;
    const int s2 = t & 31, cg = t >> 5;    // thread: 2 slots x 16 channels

    const __half2* y3h2 = (const __half2*)(g_y3h + (size_t)p*(C3*SL));
    float m0 = -INFINITY, m1 = -INFINITY;
    #pragma unroll 4
    for (int ci = 0; ci < 16; ci++) {
        int c = cg*16 + ci;
        float a = g_a3[c], d = g_d3[c];
        float2 f = __half22float2(y3h2[c*32 + s2]);
        m0 = fmaxf(m0, fmaf(a, f.x, d));
        m1 = fmaxf(m1, fmaf(a, f.y, d));
    }
    pm[cg][2*s2]   = m0;
    pm[cg][2*s2+1] = m1;
    __syncthreads();

    if (t < SL) {
        float mm = pm[0][t];
        #pragma unroll
        for (int g = 1; g < 8; g++) mm = fmaxf(mm, pm[g][t]);
        sc[t] = fmaxf(mm, 0.f);     // relu then max == max then relu
    }
    __syncthreads();

    if (t < SL) {
        float mx = sc[0];
        #pragma unroll 8
        for (int i = 1; i < SL; i++) mx = fmaxf(mx, sc[i]);
        ex[t] = expf(sc[t] - mx);
    }
    __syncthreads();

    if (t < SL) {
        float ssum = 0.f;
        #pragma unroll 8
        for (int i = 0; i < SL; i++) ssum += ex[i];
        float w = ex[t] / ssum;
        float4 f = ((const float4*)g_feats)[(size_t)p*SL + t];
        rx[t] = w*f.x; ry[t] = w*f.y; rz[t] = w*f.z;
    }
    __syncthreads();

    for (int off = 32; off >= 1; off >>= 1) {
        if (t < off) { rx[t] += rx[t+off]; ry[t] += ry[t+off]; rz[t] += rz[t+off]; }
        __syncthreads();
    }

    if (t == 0) {
        const int b = p >> 12, n = p & (NPN-1);
        const float* q = p1 + (size_t)b*3*NPN;
        out[(size_t)b*3*NPN + n]          = q[n]        + rx[0];
        out[(size_t)b*3*NPN + NPN + n]    = q[NPN+n]    + ry[0];
        out[(size_t)b*3*NPN + 2*NPN + n]  = q[2*NPN+n]  + rz[0];
    }
}

// --------------------------------------------------------------------------
extern "C" void kernel_launch(void* const* d_in, const int* in_sizes, int n_in,
                              void* d_out, int out_size) {
    const float* points1 = (const float*)d_in[0];
    const float* points2 = (const float*)d_in[1];
    const float* W1  = (const float*)d_in[4];
    const float* b1  = (const float*)d_in[5];
    const float* g1  = (const float*)d_in[6];
    const float* be1 = (const float*)d_in[7];
    const float* W2  = (const float*)d_in[8];
    const float* b2  = (const float*)d_in[9];
    const float* g2  = (const float*)d_in[10];
    const float* be2 = (const float*)d_in[11];
    const float* W3  = (const float*)d_in[12];
    const float* b3  = (const float*)d_in[13];
    const float* g3  = (const float*)d_in[14];
    const float* be3 = (const float*)d_in[15];
    float* out = (float*)d_out;

    cudaFuncSetAttribute(layer2_kernel,
                         cudaFuncAttributeMaxDynamicSharedMemorySize, (int)L2_SMEM);

    knn_kernel<<<BB*NPN*2, 128>>>(points1, points2);                 // 1 -> ncu would be 4th? no: slot4=layer3
    stats1_kernel<<<2048, 256>>>(W1, b1, W2, W3);                    // 2
    layer2_kernel<<<NPTS/4, 256, L2_SMEM>>>(W1, b1, g1, be1, b2);    // 3
    layer3_kernel<<<NPTS/2, 256>>>(b3, g2, be2);                     // 4 -> ncu
    fin3_kernel<<<1, C3>>>(g3, be3);                                 // 5
    fuse_kernel<<<NPTS, 256>>>(points1, out);                        // 6
}

// round 12
// speedup vs baseline: 1.6056x; 1.1044x over previous
#include <cuda_runtime.h>
#include <cuda_fp16.h>
#include <math.h>

#define BB    4
#define NPN   4096          // points per batch
#define KNBR  32            // k
#define SL    64            // 2k slots
#define C1    64
#define C2    64
#define C3    128
#define NPTS  (BB*NPN)      // 16384
#define NCOLS (NPTS*SL)     // 1,048,576
#define NSTRIPE 32

// packed f32x2 FMA: acc = a*b + acc (two fp32 lanes per instruction)
#define FMA2(acc, a, b) \
    asm("fma.rn.f32x2 %0, %1, %2, %0;" : "+l"(acc) : "l"(a), "l"(b))

__device__ __forceinline__ unsigned long long pack_dup(float w) {
    unsigned long long r;
    asm("mov.b64 %0, {%1, %1};" : "=l"(r) : "f"(w));
    return r;
}
__device__ __forceinline__ void unpack2(unsigned long long v, float& lo, float& hi) {
    asm("mov.b64 {%0, %1}, %2;" : "=f"(lo), "=f"(hi) : "l"(v));
}

// ---------------- scratch (static device memory; no runtime allocation) ----
__device__ float  g_feats[(size_t)NCOLS*4];  // [point][slot][4] = resi.xyz, dist
__device__ __half g_y2h [(size_t)NCOLS*C2];  // [point][c][s] fp16
__device__ __half g_y3h [(size_t)NCOLS*C3];  // [point][c][s] fp16
__device__ float  g_W2T [C1*C2];             // [i][c]
__device__ float  g_W3T [C2*C3];             // [i][c]

__device__ double g_s1[C1], g_q1[C1];
__device__ double g_s2[NSTRIPE][C2], g_q2[NSTRIPE][C2];
__device__ double g_s3[NSTRIPE][C3], g_q3[NSTRIPE][C3];
__device__ float  g_a3[C3], g_d3[C3];

// ------------------------------------------------------------------- KNN
__device__ __forceinline__ unsigned int f2u_ordered(float f) {
    unsigned int u = __float_as_uint(f);
    return (u & 0x80000000u) ? ~u : (u | 0x80000000u);
}

__global__ __launch_bounds__(128) void knn_kernel(const float* __restrict__ p1,
                                                  const float* __restrict__ p2) {
    __shared__ __align__(16) unsigned int keys[NPN];
    __shared__ unsigned int hist[256];
    __shared__ unsigned int sel[KNBR];
    __shared__ unsigned int ties[40];
    __shared__ unsigned int s_cnt, s_tcnt, s_pref, s_kk;

    const int t   = threadIdx.x;
    const unsigned int bid = blockIdx.x;
    const int set = bid & 1;
    const int pq  = bid >> 1;
    const int b   = pq >> 12;
    const int n   = pq & (NPN-1);

    if (bid == 0) {   // fold stats zeroing into block 0
        for (int i = t; i < C1; i += 128) { g_s1[i] = 0.0; g_q1[i] = 0.0; }
        double* s2 = &g_s2[0][0]; double* q2 = &g_q2[0][0];
        for (int i = t; i < NSTRIPE*C2; i += 128) { s2[i] = 0.0; q2[i] = 0.0; }
        double* s3 = &g_s3[0][0]; double* q3 = &g_q3[0][0];
        for (int i = t; i < NSTRIPE*C3; i += 128) { s3[i] = 0.0; q3[i] = 0.0; }
    }

    const float* qb  = p1 + (size_t)b*3*NPN;
    const float* tgt = (set ? p2 : p1) + (size_t)b*3*NPN;

    const float qx = qb[n], qy = qb[NPN+n], qz = qb[2*NPN+n];
    const float qn = qx*qx + qy*qy + qz*qz;

    hist[t] = 0u; hist[t+128] = 0u;
    if (t == 0) { s_pref = 0u; s_kk = KNBR; s_cnt = 0u; s_tcnt = 0u; }
    __syncthreads();

    // distance loop, vectorized loads (4 points per iter) + fused pass-0 hist
    {
        const float4* tx4 = (const float4*)tgt;
        const float4* ty4 = (const float4*)(tgt + NPN);
        const float4* tz4 = (const float4*)(tgt + 2*NPN);
        uint4* keys4 = (uint4*)keys;
        #pragma unroll
        for (int k = 0; k < 8; k++) {
            int q = k*128 + t;            // float4 group index, 0..1023
            float4 X = tx4[q], Y = ty4[q], Z = tz4[q];
            uint4 kv;
            {
                float tn = X.x*X.x + Y.x*Y.x + Z.x*Z.x;
                float dt = qx*X.x + qy*Y.x + qz*Z.x;
                kv.x = f2u_ordered(qn + tn - 2.0f*dt);
            }
            {
                float tn = X.y*X.y + Y.y*Y.y + Z.y*Z.y;
                float dt = qx*X.y + qy*Y.y + qz*Z.y;
                kv.y = f2u_ordered(qn + tn - 2.0f*dt);
            }
            {
                float tn = X.z*X.z + Y.z*Y.z + Z.z*Z.z;
                float dt = qx*X.z + qy*Y.z + qz*Z.z;
                kv.z = f2u_ordered(qn + tn - 2.0f*dt);
            }
            {
                float tn = X.w*X.w + Y.w*Y.w + Z.w*Z.w;
                float dt = qx*X.w + qy*Y.w + qz*Z.w;
                kv.w = f2u_ordered(qn + tn - 2.0f*dt);
            }
            keys4[q] = kv;
            atomicAdd(&hist[kv.x >> 24], 1u);
            atomicAdd(&hist[kv.y >> 24], 1u);
            atomicAdd(&hist[kv.z >> 24], 1u);
            atomicAdd(&hist[kv.w >> 24], 1u);
        }
    }
    __syncthreads();

    #pragma unroll
    for (int pass = 0; pass < 4; pass++) {
        const int shift = 24 - pass*8;
        const unsigned int pref = s_pref;
        const unsigned int kk   = s_kk;
        if (t < 32) {
            const int base = t * 8;
            unsigned int vals[8];
            unsigned int s = 0;
            #pragma unroll
            for (int j = 0; j < 8; j++) { s += hist[base+j]; vals[j] = s; }
            unsigned int tot = s;
            #pragma unroll
            for (int off = 1; off < 32; off <<= 1) {
                unsigned int nb = __shfl_up_sync(0xffffffffu, tot, off);
                if (t >= off) tot += nb;
            }
            const unsigned int offset = tot - s;
            #pragma unroll
            for (int j = 0; j < 8; j++) hist[base+j] = vals[j] + offset;
        }
        __syncthreads();
        #pragma unroll
        for (int r = 0; r < 2; r++) {
            int bin = t + r*128;
            unsigned int cum  = hist[bin];
            unsigned int prev = bin ? hist[bin-1] : 0u;
            if (cum >= kk && prev < kk) {
                s_pref = pref | ((unsigned int)bin << shift);
                s_kk   = kk - prev;
            }
        }
        __syncthreads();
        if (pass < 3) {
            const unsigned int npref = s_pref;
            hist[t] = 0u; hist[t+128] = 0u;
            __syncthreads();
            const int nshift = shift - 8;
            const unsigned int nmask = 0xFFFFFFFFu << (nshift + 8);
            const uint4* keys4 = (const uint4*)keys;
            #pragma unroll
            for (int k = 0; k < 8; k++) {
                uint4 kv = keys4[k*128 + t];
                if ((kv.x & nmask) == npref) atomicAdd(&hist[(kv.x >> nshift) & 255u], 1u);
                if ((kv.y & nmask) == npref) atomicAdd(&hist[(kv.y >> nshift) & 255u], 1u);
                if ((kv.z & nmask) == npref) atomicAdd(&hist[(kv.z >> nshift) & 255u], 1u);
                if ((kv.w & nmask) == npref) atomicAdd(&hist[(kv.w >> nshift) & 255u], 1u);
            }
            __syncthreads();
        }
    }

    const unsigned int T = s_pref;   // 32nd-smallest key
    {
        const uint4* keys4 = (const uint4*)keys;
        #pragma unroll
        for (int k = 0; k < 8; k++) {
            int q = k*128 + t;
            uint4 kv = keys4[q];
            unsigned int j0 = (unsigned)(q*4);
            #pragma unroll
            for (int m = 0; m < 4; m++) {
                unsigned int key = (m==0)?kv.x:(m==1)?kv.y:(m==2)?kv.z:kv.w;
                if (key < T) {
                    unsigned int pos = atomicAdd(&s_cnt, 1u);
                    if (pos < KNBR) sel[pos] = j0 + m;
                } else if (key == T) {
                    unsigned int tp = atomicAdd(&s_tcnt, 1u);
                    if (tp < 40u) ties[tp] = j0 + m;
                }
            }
        }
    }
    __syncthreads();

    if (t == 0) {
        unsigned int cnt = s_cnt, kk = s_kk, tc = s_tcnt;
        if (cnt > KNBR) cnt = KNBR;
        if (kk > KNBR - cnt) kk = KNBR - cnt;
        if (tc <= 40u) {
            for (unsigned int m = 0; m < kk; m++) {
                unsigned int best = 0xFFFFFFFFu, bi = m;
                for (unsigned int r = m; r < tc; r++)
                    if (ties[r] < best) { best = ties[r]; bi = r; }
                ties[bi] = ties[m]; ties[m] = best;
                sel[cnt + m] = best;
            }
        } else {
            unsigned int filled = 0;
            for (int j = 0; j < NPN && filled < kk; j++)
                if (keys[j] == T) { sel[cnt + filled] = (unsigned int)j; filled++; }
        }
    }
    __syncthreads();

    if (t < KNBR) {
        int j = (int)sel[t];
        float tx = tgt[j], ty = tgt[NPN+j], tz = tgt[2*NPN+j];
        float rx = tx - qx, ry = ty - qy, rz = tz - qz;
        float dist = sqrtf(rx*rx + ry*ry + rz*rz);
        float4* out4 = (float4*)g_feats;
        out4[(size_t)pq*SL + set*KNBR + t] = make_float4(rx, ry, rz, dist);
    }
}

// ----------------- layer-1 BN statistics (+ weight transposes in block 0) --
__global__ __launch_bounds__(256) void stats1_kernel(const float* __restrict__ W1,
                                                     const float* __restrict__ b1,
                                                     const float* __restrict__ W2,
                                                     const float* __restrict__ W3) {
    __shared__ float w1s[C1*4];
    __shared__ float b1s[C1];
    __shared__ float ssum[C1], ssq[C1];
    const int t = threadIdx.x;

    if (blockIdx.x == 0) {
        for (int idx = t; idx < C2*C1; idx += 256) {
            int c = idx >> 6, i = idx & 63;
            g_W2T[i*C2 + c] = W2[idx];
        }
        for (int idx = t; idx < C3*C2; idx += 256) {
            int c = idx >> 6, i = idx & 63;
            g_W3T[i*C3 + c] = W3[idx];
        }
    }

    if (t < C1*4) w1s[t] = W1[t];
    if (t < C1)  { b1s[t] = b1[t]; ssum[t] = 0.f; ssq[t] = 0.f; }
    __syncthreads();

    const int c = t & 63, g = t >> 6;
    const int COLS_PER_BLOCK = NCOLS / 2048;
    const int col0 = blockIdx.x * COLS_PER_BLOCK;
    const float w0 = w1s[c*4+0], w1 = w1s[c*4+1], w2 = w1s[c*4+2], w3 = w1s[c*4+3];
    const float bc = b1s[c];
    float sum = 0.f, sq = 0.f;
    const float4* f4 = (const float4*)g_feats;
    for (int col = col0 + g; col < col0 + COLS_PER_BLOCK; col += 4) {
        float4 f = f4[col];
        float y = fmaf(w0, f.x, fmaf(w1, f.y, fmaf(w2, f.z, fmaf(w3, f.w, bc))));
        sum += y; sq = fmaf(y, y, sq);
    }
    atomicAdd(&ssum[c], sum);
    atomicAdd(&ssq[c],  sq);
    __syncthreads();
    if (t < C1) {
        atomicAdd(&g_s1[t], (double)ssum[t]);
        atomicAdd(&g_q1[t], (double)ssq[t]);
    }
}

// ------------------------------------ layer2: x2=relu(bn1(y1)), y2=W2 x2+b2
// 4 pts/block (R9 config). y2 stored fp16.
#define L2_XS    0
#define L2_FSH   (L2_XS + 4*4096)
#define L2_W1    (L2_FSH + 1024)
#define L2_B1    (L2_W1 + 256)
#define L2_A1    (L2_B1 + 64)
#define L2_D1    (L2_A1 + 64)
#define L2_SSUM  (L2_D1 + 64)
#define L2_SSQ   (L2_SSUM + 64)
#define L2_SMEM  ((L2_SSQ + 64) * sizeof(float))

__global__ __launch_bounds__(256, 2) void layer2_kernel(const float* __restrict__ W1,
                                                        const float* __restrict__ b1,
                                                        const float* __restrict__ g1,
                                                        const float* __restrict__ be1,
                                                        const float* __restrict__ b2) {
    extern __shared__ __align__(16) float sm[];
    float* xs   = sm + L2_XS;
    float* fsh  = sm + L2_FSH;
    float* w1s  = sm + L2_W1;
    float* b1s  = sm + L2_B1;
    float* a1s  = sm + L2_A1;
    float* d1s  = sm + L2_D1;
    float* ssum = sm + L2_SSUM;
    float* ssq  = sm + L2_SSQ;

    const int t  = threadIdx.x;
    const int p0 = blockIdx.x * 4;

    w1s[t] = W1[t];
    if (t < 64) {
        b1s[t] = b1[t]; ssum[t] = 0.f; ssq[t] = 0.f;
        const double cnt = (double)NCOLS;
        double m = g_s1[t] / cnt;
        double v = g_q1[t] / cnt - m*m;
        if (v < 0.0) v = 0.0;
        double a = (double)g1[t] / sqrt(v + 1e-3);
        a1s[t] = (float)a;
        d1s[t] = (float)((double)be1[t] - a*m);
    }
    ((float4*)fsh)[t] = ((const float4*)g_feats)[(size_t)p0*SL + t];
    __syncthreads();

    {
        const float4* fsh4 = (const float4*)fsh;
        #pragma unroll 4
        for (int k = 0; k < 64; k++) {
            int idx = k*256 + t;
            int pt = idx >> 12;
            int i  = (idx >> 6) & 63;
            int s  = idx & 63;
            float4 f = fsh4[pt*SL + s];
            float y = fmaf(w1s[i*4+0], f.x, fmaf(w1s[i*4+1], f.y,
                      fmaf(w1s[i*4+2], f.z, fmaf(w1s[i*4+3], f.w, b1s[i]))));
            xs[pt*4096 + i*64 + s] = fmaxf(fmaf(a1s[i], y, d1s[i]), 0.f);
        }
    }
    __syncthreads();

    const int pt = t >> 6, wt_tid = t & 63;
    const int cq = wt_tid & 15, sg = wt_tid >> 4;
    const float* xp = xs + pt*4096 + sg*16;
    const float4* wrow = ((const float4*)g_W2T) + cq;

    unsigned long long acc[32];
    #pragma unroll
    for (int j = 0; j < 32; j++) acc[j] = 0ull;

    float4 wv = __ldg(wrow);
    ulonglong2 u0, u1, u2, u3;
    { const ulonglong2* xr = (const ulonglong2*)xp;
      u0 = xr[0]; u1 = xr[1]; u2 = xr[2]; u3 = xr[3]; }

    #pragma unroll 2
    for (int i = 0; i < C1; i++) {
        const int inext = (i < C1-1) ? i+1 : i;
        float4 wn = __ldg(wrow + inext*16);
        const ulonglong2* xn = (const ulonglong2*)(xp + inext*64);
        ulonglong2 n0 = xn[0], n1 = xn[1], n2 = xn[2], n3 = xn[3];

        unsigned long long w0 = pack_dup(wv.x), w1 = pack_dup(wv.y);
        unsigned long long w2 = pack_dup(wv.z), w3 = pack_dup(wv.w);
        FMA2(acc[ 0], w0, u0.x); FMA2(acc[ 1], w0, u0.y);
        FMA2(acc[ 2], w0, u1.x); FMA2(acc[ 3], w0, u1.y);
        FMA2(acc[ 4], w0, u2.x); FMA2(acc[ 5], w0, u2.y);
        FMA2(acc[ 6], w0, u3.x); FMA2(acc[ 7], w0, u3.y);
        FMA2(acc[ 8], w1, u0.x); FMA2(acc[ 9], w1, u0.y);
        FMA2(acc[10], w1, u1.x); FMA2(acc[11], w1, u1.y);
        FMA2(acc[12], w1, u2.x); FMA2(acc[13], w1, u2.y);
        FMA2(acc[14], w1, u3.x); FMA2(acc[15], w1, u3.y);
        FMA2(acc[16], w2, u0.x); FMA2(acc[17], w2, u0.y);
        FMA2(acc[18], w2, u1.x); FMA2(acc[19], w2, u1.y);
        FMA2(acc[20], w2, u2.x); FMA2(acc[21], w2, u2.y);
        FMA2(acc[22], w2, u3.x); FMA2(acc[23], w2, u3.y);
        FMA2(acc[24], w3, u0.x); FMA2(acc[25], w3, u0.y);
        FMA2(acc[26], w3, u1.x); FMA2(acc[27], w3, u1.y);
        FMA2(acc[28], w3, u2.x); FMA2(acc[29], w3, u2.y);
        FMA2(acc[30], w3, u3.x); FMA2(acc[31], w3, u3.y);

        wv = wn; u0 = n0; u1 = n1; u2 = n2; u3 = n3;
    }

    __half* ybase = g_y2h + (size_t)(p0 + pt)*(C2*SL) + sg*16;
    #pragma unroll
    for (int cc = 0; cc < 4; cc++) {
        const int c = cq*4 + cc;
        const float bc = b2[c];
        float v[16];
        #pragma unroll
        for (int sp = 0; sp < 8; sp++)
            unpack2(acc[cc*8 + sp], v[2*sp], v[2*sp+1]);
        float csum = 0.f, csq = 0.f;
        #pragma unroll
        for (int j = 0; j < 16; j++) {
            v[j] += bc; csum += v[j]; csq = fmaf(v[j], v[j], csq);
        }
        uint4 pk0, pk1;
        __half2 h;
        h = __floats2half2_rn(v[0],  v[1]);  pk0.x = *(unsigned int*)&h;
        h = __floats2half2_rn(v[2],  v[3]);  pk0.y = *(unsigned int*)&h;
        h = __floats2half2_rn(v[4],  v[5]);  pk0.z = *(unsigned int*)&h;
        h = __floats2half2_rn(v[6],  v[7]);  pk0.w = *(unsigned int*)&h;
        h = __floats2half2_rn(v[8],  v[9]);  pk1.x = *(unsigned int*)&h;
        h = __floats2half2_rn(v[10], v[11]); pk1.y = *(unsigned int*)&h;
        h = __floats2half2_rn(v[12], v[13]); pk1.z = *(unsigned int*)&h;
        h = __floats2half2_rn(v[14], v[15]); pk1.w = *(unsigned int*)&h;
        uint4* o = (uint4*)(ybase + c*64);
        o[0] = pk0; o[1] = pk1;
        atomicAdd(&ssum[c], csum);
        atomicAdd(&ssq[c],  csq);
    }
    __syncthreads();
    if (t < C2) {
        int r = blockIdx.x & (NSTRIPE-1);
        atomicAdd(&g_s2[r][t], (double)ssum[t]);
        atomicAdd(&g_q2[r][t], (double)ssq[t]);
    }
}

// ------------------------------------ layer3: x3=relu(bn2(y2)), y3=W3 x3+b3
// R9 config: 2 pts/block, 32 acc, pipelined, parallel BN2 finalize, fp16 I/O.
__global__ __launch_bounds__(256, 2) void layer3_kernel(const float* __restrict__ b3,
                                                        const float* __restrict__ g2,
                                                        const float* __restrict__ be2) {
    __shared__ __align__(16) float xs[2*4096];
    __shared__ float a2s[C2], d2s[C2];
    __shared__ float ssum[C3], ssq[C3];

    const int t  = threadIdx.x;
    const int p0 = blockIdx.x * 2;

    {   // parallel BN2 finalize: 4 groups x 8 stripes, reduce in xs alias
        double* red_s = (double*)xs;
        double* red_q = ((double*)xs) + 256;
        const int ch = t & 63, grp = t >> 6;
        double s = 0.0, q = 0.0;
        #pragma unroll
        for (int r = 0; r < 8; r++) {
            s += g_s2[grp*8 + r][ch];
            q += g_q2[grp*8 + r][ch];
        }
        red_s[t] = s; red_q[t] = q;
        __syncthreads();
        if (t < 64) {
            double ss = (red_s[t] + red_s[t+64]) + (red_s[t+128] + red_s[t+192]);
            double qq = (red_q[t] + red_q[t+64]) + (red_q[t+128] + red_q[t+192]);
            const double cnt = (double)NCOLS;
            double m = ss / cnt;
            double v = qq / cnt - m*m;
            if (v < 0.0) v = 0.0;
            double a = (double)g2[t] / sqrt(v + 1e-3);
            a2s[t] = (float)a;
            d2s[t] = (float)((double)be2[t] - a*m);
        }
        if (t < 128) { ssum[t] = 0.f; ssq[t] = 0.f; }
        __syncthreads();
    }

    {   // x3 into smem from fp16 y2: 1024 uint4 (8 halves each), 4 per thread
        const uint4* y2p = (const uint4*)(g_y2h + (size_t)p0*(C2*SL));
        float4* xs4 = (float4*)xs;
        #pragma unroll
        for (int k = 0; k < 4; k++) {
            int idx = k*256 + t;               // 0..1023
            int i = (idx >> 3) & 63;           // 8 halves per uint4, 64 per row
            float a = a2s[i], d = d2s[i];
            uint4 pk = __ldg(&y2p[idx]);
            float2 f0 = __half22float2(*(__half2*)&pk.x);
            float2 f1 = __half22float2(*(__half2*)&pk.y);
            float2 f2 = __half22float2(*(__half2*)&pk.z);
            float2 f3 = __half22float2(*(__half2*)&pk.w);
            float4 xa, xb;
            xa.x = fmaxf(fmaf(a, f0.x, d), 0.f);
            xa.y = fmaxf(fmaf(a, f0.y, d), 0.f);
            xa.z = fmaxf(fmaf(a, f1.x, d), 0.f);
            xa.w = fmaxf(fmaf(a, f1.y, d), 0.f);
            xb.x = fmaxf(fmaf(a, f2.x, d), 0.f);
            xb.y = fmaxf(fmaf(a, f2.y, d), 0.f);
            xb.z = fmaxf(fmaf(a, f3.x, d), 0.f);
            xb.w = fmaxf(fmaf(a, f3.y, d), 0.f);
            xs4[idx*2]     = xa;
            xs4[idx*2 + 1] = xb;
        }
    }
    __syncthreads();

    const int pt = t >> 7, wt_tid = t & 127;
    const int cq = wt_tid & 31, sg = wt_tid >> 5;
    const float* xp = xs + pt*4096 + sg*16;
    const float4* wrow = ((const float4*)g_W3T) + cq;

    unsigned long long acc[32];
    #pragma unroll
    for (int j = 0; j < 32; j++) acc[j] = 0ull;

    float4 wv = __ldg(wrow);
    ulonglong2 u0, u1, u2, u3;
    { const ulonglong2* xr = (const ulonglong2*)xp;
      u0 = xr[0]; u1 = xr[1]; u2 = xr[2]; u3 = xr[3]; }

    #pragma unroll 2
    for (int i = 0; i < C2; i++) {
        const int inext = (i < C2-1) ? i+1 : i;
        float4 wn = __ldg(wrow + inext*32);
        const ulonglong2* xn = (const ulonglong2*)(xp + inext*64);
        ulonglong2 n0 = xn[0], n1 = xn[1], n2 = xn[2], n3 = xn[3];

        unsigned long long w0 = pack_dup(wv.x), w1 = pack_dup(wv.y);
        unsigned long long w2 = pack_dup(wv.z), w3 = pack_dup(wv.w);
        FMA2(acc[ 0], w0, u0.x); FMA2(acc[ 1], w0, u0.y);
        FMA2(acc[ 2], w0, u1.x); FMA2(acc[ 3], w0, u1.y);
        FMA2(acc[ 4], w0, u2.x); FMA2(acc[ 5], w0, u2.y);
        FMA2(acc[ 6], w0, u3.x); FMA2(acc[ 7], w0, u3.y);
        FMA2(acc[ 8], w1, u0.x); FMA2(acc[ 9], w1, u0.y);
        FMA2(acc[10], w1, u1.x); FMA2(acc[11], w1, u1.y);
        FMA2(acc[12], w1, u2.x); FMA2(acc[13], w1, u2.y);
        FMA2(acc[14], w1, u3.x); FMA2(acc[15], w1, u3.y);
        FMA2(acc[16], w2, u0.x); FMA2(acc[17], w2, u0.y);
        FMA2(acc[18], w2, u1.x); FMA2(acc[19], w2, u1.y);
        FMA2(acc[20], w2, u2.x); FMA2(acc[21], w2, u2.y);
        FMA2(acc[22], w2, u3.x); FMA2(acc[23], w2, u3.y);
        FMA2(acc[24], w3, u0.x); FMA2(acc[25], w3, u0.y);
        FMA2(acc[26], w3, u1.x); FMA2(acc[27], w3, u1.y);
        FMA2(acc[28], w3, u2.x); FMA2(acc[29], w3, u2.y);
        FMA2(acc[30], w3, u3.x); FMA2(acc[31], w3, u3.y);

        wv = wn; u0 = n0; u1 = n1; u2 = n2; u3 = n3;
    }

    __half* ybase = g_y3h + (size_t)(p0 + pt)*(C3*SL) + sg*16;
    #pragma unroll
    for (int cc = 0; cc < 4; cc++) {
        const int c = cq*4 + cc;
        const float bc = b3[c];
        float v[16];
        #pragma unroll
        for (int sp = 0; sp < 8; sp++)
            unpack2(acc[cc*8 + sp], v[2*sp], v[2*sp+1]);
        float csum = 0.f, csq = 0.f;
        #pragma unroll
        for (int j = 0; j < 16; j++) {
            v[j] += bc; csum += v[j]; csq = fmaf(v[j], v[j], csq);
        }
        uint4 pk0, pk1;
        __half2 h;
        h = __floats2half2_rn(v[0],  v[1]);  pk0.x = *(unsigned int*)&h;
        h = __floats2half2_rn(v[2],  v[3]);  pk0.y = *(unsigned int*)&h;
        h = __floats2half2_rn(v[4],  v[5]);  pk0.z = *(unsigned int*)&h;
        h = __floats2half2_rn(v[6],  v[7]);  pk0.w = *(unsigned int*)&h;
        h = __floats2half2_rn(v[8],  v[9]);  pk1.x = *(unsigned int*)&h;
        h = __floats2half2_rn(v[10], v[11]); pk1.y = *(unsigned int*)&h;
        h = __floats2half2_rn(v[12], v[13]); pk1.z = *(unsigned int*)&h;
        h = __floats2half2_rn(v[14], v[15]); pk1.w = *(unsigned int*)&h;
        uint4* o = (uint4*)(ybase + c*64);
        o[0] = pk0; o[1] = pk1;
        atomicAdd(&ssum[c], csum);
        atomicAdd(&ssq[c],  csq);
    }
    __syncthreads();
    if (t < C3) {
        int r = blockIdx.x & (NSTRIPE-1);
        atomicAdd(&g_s3[r][t], (double)ssum[t]);
        atomicAdd(&g_q3[r][t], (double)ssq[t]);
    }
}

__global__ void fin3_kernel(const float* __restrict__ g3, const float* __restrict__ be3) {
    int c = threadIdx.x;   // 128
    double s = 0.0, q = 0.0;
    for (int r = 0; r < NSTRIPE; r++) { s += g_s3[r][c]; q += g_q3[r][c]; }
    const double cnt = (double)NCOLS;
    double m = s / cnt;
    double v = q / cnt - m*m;
    if (v < 0.0) v = 0.0;
    double a = (double)g3[c] / sqrt(v + 1e-3);
    g_a3[c] = (float)a;
    g_d3[c] = (float)((double)be3[c] - a*m);
}

// --------------------------- max over channels, softmax over slots, fuse ---
__global__ __launch_bounds__(256) void fuse_kernel(const float* __restrict__ p1,
                                                   float* __restrict__ out) {
    __shared__ float pm[8][SL];
    __shared__ float sc[SL];
    __shared__ float ex[SL];
    __shared__ float rx[SL], ry[SL], rz[SL];

    const int t = threadIdx.x;
    const int p = blockIdx.x;
    const int s2 = t & 31, cg = t >> 5;    // thread: 2 slots x 16 channels

    const __half2* y3h2 = (const __half2*)(g_y3h + (size_t)p*(C3*SL));
    float m0 = -INFINITY, m1 = -INFINITY;
    #pragma unroll 4
    for (int ci = 0; ci < 16; ci++) {
        int c = cg*16 + ci;
        float a = g_a3[c], d = g_d3[c];
        float2 f = __half22float2(y3h2[c*32 + s2]);
        m0 = fmaxf(m0, fmaf(a, f.x, d));
        m1 = fmaxf(m1, fmaf(a, f.y, d));
    }
    pm[cg][2*s2]   = m0;
    pm[cg][2*s2+1] = m1;
    __syncthreads();

    if (t < SL) {
        float mm = pm[0][t];
        #pragma unroll
        for (int g = 1; g < 8; g++) mm = fmaxf(mm, pm[g][t]);
        sc[t] = fmaxf(mm, 0.f);     // relu then max == max then relu
    }
    __syncthreads();

    if (t < SL) {
        float mx = sc[0];
        #pragma unroll 8
        for (int i = 1; i < SL; i++) mx = fmaxf(mx, sc[i]);
        ex[t] = expf(sc[t] - mx);
    }
    __syncthreads();

    if (t < SL) {
        float ssum = 0.f;
        #pragma unroll 8
        for (int i = 0; i < SL; i++) ssum += ex[i];
        float w = ex[t] / ssum;
        float4 f = ((const float4*)g_feats)[(size_t)p*SL + t];
        rx[t] = w*f.x; ry[t] = w*f.y; rz[t] = w*f.z;
    }
    __syncthreads();

    for (int off = 32; off >= 1; off >>= 1) {
        if (t < off) { rx[t] += rx[t+off]; ry[t] += ry[t+off]; rz[t] += rz[t+off]; }
        __syncthreads();
    }

    if (t == 0) {
        const int b = p >> 12, n = p & (NPN-1);
        const float* q = p1 + (size_t)b*3*NPN;
        out[(size_t)b*3*NPN + n]          = q[n]        + rx[0];
        out[(size_t)b*3*NPN + NPN + n]    = q[NPN+n]    + ry[0];
        out[(size_t)b*3*NPN + 2*NPN + n]  = q[2*NPN+n]  + rz[0];
    }
}

// --------------------------------------------------------------------------
extern "C" void kernel_launch(void* const* d_in, const int* in_sizes, int n_in,
                              void* d_out, int out_size) {
    const float* points1 = (const float*)d_in[0];
    const float* points2 = (const float*)d_in[1];
    const float* W1  = (const float*)d_in[4];
    const float* b1  = (const float*)d_in[5];
    const float* g1  = (const float*)d_in[6];
    const float* be1 = (const float*)d_in[7];
    const float* W2  = (const float*)d_in[8];
    const float* b2  = (const float*)d_in[9];
    const float* g2  = (const float*)d_in[10];
    const float* be2 = (const float*)d_in[11];
    const float* W3  = (const float*)d_in[12];
    const float* b3  = (const float*)d_in[13];
    const float* g3  = (const float*)d_in[14];
    const float* be3 = (const float*)d_in[15];
    float* out = (float*)d_out;

    cudaFuncSetAttribute(layer2_kernel,
                         cudaFuncAttributeMaxDynamicSharedMemorySize, (int)L2_SMEM);

    knn_kernel<<<BB*NPN*2, 128>>>(points1, points2);                 // 1
    stats1_kernel<<<2048, 256>>>(W1, b1, W2, W3);                    // 2
    layer2_kernel<<<NPTS/4, 256, L2_SMEM>>>(W1, b1, g1, be1, b2);    // 3
    layer3_kernel<<<NPTS/2, 256>>>(b3, g2, be2);                     // 4 -> ncu
    fin3_kernel<<<1, C3>>>(g3, be3);                                 // 5
    fuse_kernel<<<NPTS, 256>>>(points1, out);                        // 6
}

// round 14
// speedup vs baseline: 1.6990x; 1.0582x over previous
#include <cuda_runtime.h>
#include <cuda_fp16.h>
#include <math.h>

#define BB    4
#define NPN   4096          // points per batch
#define KNBR  32            // k
#define SL    64            // 2k slots
#define C1    64
#define C2    64
#define C3    128
#define NPTS  (BB*NPN)      // 16384
#define NCOLS (NPTS*SL)     // 1,048,576
#define NSTRIPE 32
#define WPAD  72            // padded row stride (halves) for ldmatrix tiles

// packed f32x2 FMA: acc = a*b + acc (two fp32 lanes per instruction)
#define FMA2(acc, a, b) \
    asm("fma.rn.f32x2 %0, %1, %2, %0;" : "+l"(acc) : "l"(a), "l"(b))

__device__ __forceinline__ unsigned long long pack_dup(float w) {
    unsigned long long r;
    asm("mov.b64 %0, {%1, %1};" : "=l"(r) : "f"(w));
    return r;
}
__device__ __forceinline__ void unpack2(unsigned long long v, float& lo, float& hi) {
    asm("mov.b64 {%0, %1}, %2;" : "=f"(lo), "=f"(hi) : "l"(v));
}
__device__ __forceinline__ unsigned int smem_u32(const void* p) {
    unsigned int a;
    asm("{ .reg .u64 t; cvta.to.shared.u64 t, %1; cvt.u32.u64 %0, t; }"
        : "=r"(a) : "l"(p));
    return a;
}

// ---------------- scratch (static device memory; no runtime allocation) ----
__device__ float  g_feats[(size_t)NCOLS*4];  // [point][slot][4] = resi.xyz, dist
__device__ __half g_y2h [(size_t)NCOLS*C2];  // [point][c][s] fp16
__device__ __half g_y3h [(size_t)NCOLS*C3];  // [point][c][s] fp16
__device__ float  g_W2T [C1*C2];             // [i][c]
__device__ __align__(16) __half g_W3Hp[C3*WPAD];  // W3 fp16, padded rows

__device__ double g_s1[C1], g_q1[C1];
__device__ double g_s2[NSTRIPE][C2], g_q2[NSTRIPE][C2];
__device__ double g_s3[NSTRIPE][C3], g_q3[NSTRIPE][C3];
__device__ float  g_a3[C3], g_d3[C3];

// ------------------------------------------------------------------- KNN
__device__ __forceinline__ unsigned int f2u_ordered(float f) {
    unsigned int u = __float_as_uint(f);
    return (u & 0x80000000u) ? ~u : (u | 0x80000000u);
}

__global__ __launch_bounds__(128) void knn_kernel(const float* __restrict__ p1,
                                                  const float* __restrict__ p2) {
    __shared__ __align__(16) unsigned int keys[NPN];
    __shared__ unsigned int hist[256];
    __shared__ unsigned int sel[KNBR];
    __shared__ unsigned int ties[40];
    __shared__ unsigned int s_cnt, s_tcnt, s_pref, s_kk;

    const int t   = threadIdx.x;
    const unsigned int bid = blockIdx.x;
    const int set = bid & 1;
    const int pq  = bid >> 1;
    const int b   = pq >> 12;
    const int n   = pq & (NPN-1);

    if (bid == 0) {   // fold stats zeroing into block 0
        for (int i = t; i < C1; i += 128) { g_s1[i] = 0.0; g_q1[i] = 0.0; }
        double* s2 = &g_s2[0][0]; double* q2 = &g_q2[0][0];
        for (int i = t; i < NSTRIPE*C2; i += 128) { s2[i] = 0.0; q2[i] = 0.0; }
        double* s3 = &g_s3[0][0]; double* q3 = &g_q3[0][0];
        for (int i = t; i < NSTRIPE*C3; i += 128) { s3[i] = 0.0; q3[i] = 0.0; }
    }

    const float* qb  = p1 + (size_t)b*3*NPN;
    const float* tgt = (set ? p2 : p1) + (size_t)b*3*NPN;

    const float qx = qb[n], qy = qb[NPN+n], qz = qb[2*NPN+n];
    const float qn = qx*qx + qy*qy + qz*qz;

    hist[t] = 0u; hist[t+128] = 0u;
    if (t == 0) { s_pref = 0u; s_kk = KNBR; s_cnt = 0u; s_tcnt = 0u; }
    __syncthreads();

    {
        const float4* tx4 = (const float4*)tgt;
        const float4* ty4 = (const float4*)(tgt + NPN);
        const float4* tz4 = (const float4*)(tgt + 2*NPN);
        uint4* keys4 = (uint4*)keys;
        #pragma unroll
        for (int k = 0; k < 8; k++) {
            int q = k*128 + t;
            float4 X = tx4[q], Y = ty4[q], Z = tz4[q];
            uint4 kv;
            { float tn = X.x*X.x + Y.x*Y.x + Z.x*Z.x;
              float dt = qx*X.x + qy*Y.x + qz*Z.x;
              kv.x = f2u_ordered(qn + tn - 2.0f*dt); }
            { float tn = X.y*X.y + Y.y*Y.y + Z.y*Z.y;
              float dt = qx*X.y + qy*Y.y + qz*Z.y;
              kv.y = f2u_ordered(qn + tn - 2.0f*dt); }
            { float tn = X.z*X.z + Y.z*Y.z + Z.z*Z.z;
              float dt = qx*X.z + qy*Y.z + qz*Z.z;
              kv.z = f2u_ordered(qn + tn - 2.0f*dt); }
            { float tn = X.w*X.w + Y.w*Y.w + Z.w*Z.w;
              float dt = qx*X.w + qy*Y.w + qz*Z.w;
              kv.w = f2u_ordered(qn + tn - 2.0f*dt); }
            keys4[q] = kv;
            atomicAdd(&hist[kv.x >> 24], 1u);
            atomicAdd(&hist[kv.y >> 24], 1u);
            atomicAdd(&hist[kv.z >> 24], 1u);
            atomicAdd(&hist[kv.w >> 24], 1u);
        }
    }
    __syncthreads();

    #pragma unroll
    for (int pass = 0; pass < 4; pass++) {
        const int shift = 24 - pass*8;
        const unsigned int pref = s_pref;
        const unsigned int kk   = s_kk;
        if (t < 32) {
            const int base = t * 8;
            unsigned int vals[8];
            unsigned int s = 0;
            #pragma unroll
            for (int j = 0; j < 8; j++) { s += hist[base+j]; vals[j] = s; }
            unsigned int tot = s;
            #pragma unroll
            for (int off = 1; off < 32; off <<= 1) {
                unsigned int nb = __shfl_up_sync(0xffffffffu, tot, off);
                if (t >= off) tot += nb;
            }
            const unsigned int offset = tot - s;
            #pragma unroll
            for (int j = 0; j < 8; j++) hist[base+j] = vals[j] + offset;
        }
        __syncthreads();
        #pragma unroll
        for (int r = 0; r < 2; r++) {
            int bin = t + r*128;
            unsigned int cum  = hist[bin];
            unsigned int prev = bin ? hist[bin-1] : 0u;
            if (cum >= kk && prev < kk) {
                s_pref = pref | ((unsigned int)bin << shift);
                s_kk   = kk - prev;
            }
        }
        __syncthreads();
        if (pass < 3) {
            const unsigned int npref = s_pref;
            hist[t] = 0u; hist[t+128] = 0u;
            __syncthreads();
            const int nshift = shift - 8;
            const unsigned int nmask = 0xFFFFFFFFu << (nshift + 8);
            const uint4* keys4 = (const uint4*)keys;
            #pragma unroll
            for (int k = 0; k < 8; k++) {
                uint4 kv = keys4[k*128 + t];
                if ((kv.x & nmask) == npref) atomicAdd(&hist[(kv.x >> nshift) & 255u], 1u);
                if ((kv.y & nmask) == npref) atomicAdd(&hist[(kv.y >> nshift) & 255u], 1u);
                if ((kv.z & nmask) == npref) atomicAdd(&hist[(kv.z >> nshift) & 255u], 1u);
                if ((kv.w & nmask) == npref) atomicAdd(&hist[(kv.w >> nshift) & 255u], 1u);
            }
            __syncthreads();
        }
    }

    const unsigned int T = s_pref;
    {
        const uint4* keys4 = (const uint4*)keys;
        #pragma unroll
        for (int k = 0; k < 8; k++) {
            int q = k*128 + t;
            uint4 kv = keys4[q];
            unsigned int j0 = (unsigned)(q*4);
            #pragma unroll
            for (int m = 0; m < 4; m++) {
                unsigned int key = (m==0)?kv.x:(m==1)?kv.y:(m==2)?kv.z:kv.w;
                if (key < T) {
                    unsigned int pos = atomicAdd(&s_cnt, 1u);
                    if (pos < KNBR) sel[pos] = j0 + m;
                } else if (key == T) {
                    unsigned int tp = atomicAdd(&s_tcnt, 1u);
                    if (tp < 40u) ties[tp] = j0 + m;
                }
            }
        }
    }
    __syncthreads();

    if (t == 0) {
        unsigned int cnt = s_cnt, kk = s_kk, tc = s_tcnt;
        if (cnt > KNBR) cnt = KNBR;
        if (kk > KNBR - cnt) kk = KNBR - cnt;
        if (tc <= 40u) {
            for (unsigned int m = 0; m < kk; m++) {
                unsigned int best = 0xFFFFFFFFu, bi = m;
                for (unsigned int r = m; r < tc; r++)
                    if (ties[r] < best) { best = ties[r]; bi = r; }
                ties[bi] = ties[m]; ties[m] = best;
                sel[cnt + m] = best;
            }
        } else {
            unsigned int filled = 0;
            for (int j = 0; j < NPN && filled < kk; j++)
                if (keys[j] == T) { sel[cnt + filled] = (unsigned int)j; filled++; }
        }
    }
    __syncthreads();

    if (t < KNBR) {
        int j = (int)sel[t];
        float tx = tgt[j], ty = tgt[NPN+j], tz = tgt[2*NPN+j];
        float rx = tx - qx, ry = ty - qy, rz = tz - qz;
        float dist = sqrtf(rx*rx + ry*ry + rz*rz);
        float4* out4 = (float4*)g_feats;
        out4[(size_t)pq*SL + set*KNBR + t] = make_float4(rx, ry, rz, dist);
    }
}

// --------- layer-1 BN statistics (+ W2T / padded fp16 W3 in block 0) -------
__global__ __launch_bounds__(256) void stats1_kernel(const float* __restrict__ W1,
                                                     const float* __restrict__ b1,
                                                     const float* __restrict__ W2,
                                                     const float* __restrict__ W3) {
    __shared__ float w1s[C1*4];
    __shared__ float b1s[C1];
    __shared__ float ssum[C1], ssq[C1];
    const int t = threadIdx.x;

    if (blockIdx.x == 0) {
        for (int idx = t; idx < C2*C1; idx += 256) {
            int c = idx >> 6, i = idx & 63;
            g_W2T[i*C2 + c] = W2[idx];
        }
        // W3 fp16 with padded rows (WPAD halves) for conflict-free ldmatrix
        for (int idx = t; idx < C3*C2; idx += 256) {
            int m = idx >> 6, k = idx & 63;
            g_W3Hp[m*WPAD + k] = __float2half_rn(W3[idx]);
        }
    }

    if (t < C1*4) w1s[t] = W1[t];
    if (t < C1)  { b1s[t] = b1[t]; ssum[t] = 0.f; ssq[t] = 0.f; }
    __syncthreads();

    const int c = t & 63, g = t >> 6;
    const int COLS_PER_BLOCK = NCOLS / 2048;
    const int col0 = blockIdx.x * COLS_PER_BLOCK;
    const float w0 = w1s[c*4+0], w1 = w1s[c*4+1], w2 = w1s[c*4+2], w3 = w1s[c*4+3];
    const float bc = b1s[c];
    float sum = 0.f, sq = 0.f;
    const float4* f4 = (const float4*)g_feats;
    for (int col = col0 + g; col < col0 + COLS_PER_BLOCK; col += 4) {
        float4 f = f4[col];
        float y = fmaf(w0, f.x, fmaf(w1, f.y, fmaf(w2, f.z, fmaf(w3, f.w, bc))));
        sum += y; sq = fmaf(y, y, sq);
    }
    atomicAdd(&ssum[c], sum);
    atomicAdd(&ssq[c],  sq);
    __syncthreads();
    if (t < C1) {
        atomicAdd(&g_s1[t], (double)ssum[t]);
        atomicAdd(&g_q1[t], (double)ssq[t]);
    }
}

// ------------------------------------ layer2: x2=relu(bn1(y1)), y2=W2 x2+b2
#define L2_XS    0
#define L2_FSH   (L2_XS + 4*4096)
#define L2_W1    (L2_FSH + 1024)
#define L2_B1    (L2_W1 + 256)
#define L2_A1    (L2_B1 + 64)
#define L2_D1    (L2_A1 + 64)
#define L2_SSUM  (L2_D1 + 64)
#define L2_SSQ   (L2_SSUM + 64)
#define L2_SMEM  ((L2_SSQ + 64) * sizeof(float))

__global__ __launch_bounds__(256, 2) void layer2_kernel(const float* __restrict__ W1,
                                                        const float* __restrict__ b1,
                                                        const float* __restrict__ g1,
                                                        const float* __restrict__ be1,
                                                        const float* __restrict__ b2) {
    extern __shared__ __align__(16) float sm[];
    float* xs   = sm + L2_XS;
    float* fsh  = sm + L2_FSH;
    float* w1s  = sm + L2_W1;
    float* b1s  = sm + L2_B1;
    float* a1s  = sm + L2_A1;
    float* d1s  = sm + L2_D1;
    float* ssum = sm + L2_SSUM;
    float* ssq  = sm + L2_SSQ;

    const int t  = threadIdx.x;
    const int p0 = blockIdx.x * 4;

    w1s[t] = W1[t];
    if (t < 64) {
        b1s[t] = b1[t]; ssum[t] = 0.f; ssq[t] = 0.f;
        const double cnt = (double)NCOLS;
        double m = g_s1[t] / cnt;
        double v = g_q1[t] / cnt - m*m;
        if (v < 0.0) v = 0.0;
        double a = (double)g1[t] / sqrt(v + 1e-3);
        a1s[t] = (float)a;
        d1s[t] = (float)((double)be1[t] - a*m);
    }
    ((float4*)fsh)[t] = ((const float4*)g_feats)[(size_t)p0*SL + t];
    __syncthreads();

    {
        const float4* fsh4 = (const float4*)fsh;
        #pragma unroll 4
        for (int k = 0; k < 64; k++) {
            int idx = k*256 + t;
            int pt = idx >> 12;
            int i  = (idx >> 6) & 63;
            int s  = idx & 63;
            float4 f = fsh4[pt*SL + s];
            float y = fmaf(w1s[i*4+0], f.x, fmaf(w1s[i*4+1], f.y,
                      fmaf(w1s[i*4+2], f.z, fmaf(w1s[i*4+3], f.w, b1s[i]))));
            xs[pt*4096 + i*64 + s] = fmaxf(fmaf(a1s[i], y, d1s[i]), 0.f);
        }
    }
    __syncthreads();

    const int pt = t >> 6, wt_tid = t & 63;
    const int cq = wt_tid & 15, sg = wt_tid >> 4;
    const float* xp = xs + pt*4096 + sg*16;
    const float4* wrow = ((const float4*)g_W2T) + cq;

    unsigned long long acc[32];
    #pragma unroll
    for (int j = 0; j < 32; j++) acc[j] = 0ull;

    float4 wv = __ldg(wrow);
    ulonglong2 u0, u1, u2, u3;
    { const ulonglong2* xr = (const ulonglong2*)xp;
      u0 = xr[0]; u1 = xr[1]; u2 = xr[2]; u3 = xr[3]; }

    #pragma unroll 2
    for (int i = 0; i < C1; i++) {
        const int inext = (i < C1-1) ? i+1 : i;
        float4 wn = __ldg(wrow + inext*16);
        const ulonglong2* xn = (const ulonglong2*)(xp + inext*64);
        ulonglong2 n0 = xn[0], n1 = xn[1], n2 = xn[2], n3 = xn[3];

        unsigned long long w0 = pack_dup(wv.x), w1 = pack_dup(wv.y);
        unsigned long long w2 = pack_dup(wv.z), w3 = pack_dup(wv.w);
        FMA2(acc[ 0], w0, u0.x); FMA2(acc[ 1], w0, u0.y);
        FMA2(acc[ 2], w0, u1.x); FMA2(acc[ 3], w0, u1.y);
        FMA2(acc[ 4], w0, u2.x); FMA2(acc[ 5], w0, u2.y);
        FMA2(acc[ 6], w0, u3.x); FMA2(acc[ 7], w0, u3.y);
        FMA2(acc[ 8], w1, u0.x); FMA2(acc[ 9], w1, u0.y);
        FMA2(acc[10], w1, u1.x); FMA2(acc[11], w1, u1.y);
        FMA2(acc[12], w1, u2.x); FMA2(acc[13], w1, u2.y);
        FMA2(acc[14], w1, u3.x); FMA2(acc[15], w1, u3.y);
        FMA2(acc[16], w2, u0.x); FMA2(acc[17], w2, u0.y);
        FMA2(acc[18], w2, u1.x); FMA2(acc[19], w2, u1.y);
        FMA2(acc[20], w2, u2.x); FMA2(acc[21], w2, u2.y);
        FMA2(acc[22], w2, u3.x); FMA2(acc[23], w2, u3.y);
        FMA2(acc[24], w3, u0.x); FMA2(acc[25], w3, u0.y);
        FMA2(acc[26], w3, u1.x); FMA2(acc[27], w3, u1.y);
        FMA2(acc[28], w3, u2.x); FMA2(acc[29], w3, u2.y);
        FMA2(acc[30], w3, u3.x); FMA2(acc[31], w3, u3.y);

        wv = wn; u0 = n0; u1 = n1; u2 = n2; u3 = n3;
    }

    __half* ybase = g_y2h + (size_t)(p0 + pt)*(C2*SL) + sg*16;
    #pragma unroll
    for (int cc = 0; cc < 4; cc++) {
        const int c = cq*4 + cc;
        const float bc = b2[c];
        float v[16];
        #pragma unroll
        for (int sp = 0; sp < 8; sp++)
            unpack2(acc[cc*8 + sp], v[2*sp], v[2*sp+1]);
        float csum = 0.f, csq = 0.f;
        #pragma unroll
        for (int j = 0; j < 16; j++) {
            v[j] += bc; csum += v[j]; csq = fmaf(v[j], v[j], csq);
        }
        uint4 pk0, pk1;
        __half2 h;
        h = __floats2half2_rn(v[0],  v[1]);  pk0.x = *(unsigned int*)&h;
        h = __floats2half2_rn(v[2],  v[3]);  pk0.y = *(unsigned int*)&h;
        h = __floats2half2_rn(v[4],  v[5]);  pk0.z = *(unsigned int*)&h;
        h = __floats2half2_rn(v[6],  v[7]);  pk0.w = *(unsigned int*)&h;
        h = __floats2half2_rn(v[8],  v[9]);  pk1.x = *(unsigned int*)&h;
        h = __floats2half2_rn(v[10], v[11]); pk1.y = *(unsigned int*)&h;
        h = __floats2half2_rn(v[12], v[13]); pk1.z = *(unsigned int*)&h;
        h = __floats2half2_rn(v[14], v[15]); pk1.w = *(unsigned int*)&h;
        uint4* o = (uint4*)(ybase + c*64);
        o[0] = pk0; o[1] = pk1;
        atomicAdd(&ssum[c], csum);
        atomicAdd(&ssq[c],  csq);
    }
    __syncthreads();
    if (t < C2) {
        int r = blockIdx.x & (NSTRIPE-1);
        atomicAdd(&g_s2[r][t], (double)ssum[t]);
        atomicAdd(&g_q2[r][t], (double)ssq[t]);
    }
}

// ---------------- layer3 via mma.sync (HMMA): y3 = W3 x3 + b3 --------------
// 1 pt/block, 8 warps. Warp w: m-rows 16w..16w+15, all 64 slots.
// A = W3 fp16 padded rows; B = x3 fp16 padded rows (ldmatrix.trans).
__global__ __launch_bounds__(256) void layer3_kernel(const float* __restrict__ b3,
                                                     const float* __restrict__ g2,
                                                     const float* __restrict__ be2) {
    __shared__ __align__(16) __half Asm[C3*WPAD];   // 18432 B
    __shared__ __align__(16) __half Bsm[C2*WPAD];   // 9216 B
    __shared__ float a2s[C2], d2s[C2];
    __shared__ float ssum[C3], ssq[C3];

    const int t    = threadIdx.x;
    const int wid  = t >> 5;
    const int lane = t & 31;
    const int p    = blockIdx.x;

    {   // parallel BN2 finalize (reduction buffers aliased into Asm)
        double* red_s = (double*)Asm;
        double* red_q = ((double*)Asm) + 256;
        const int ch = t & 63, grp = t >> 6;
        double s = 0.0, q = 0.0;
        #pragma unroll
        for (int r = 0; r < 8; r++) {
            s += g_s2[grp*8 + r][ch];
            q += g_q2[grp*8 + r][ch];
        }
        red_s[t] = s; red_q[t] = q;
        __syncthreads();
        if (t < 64) {
            double ss = (red_s[t] + red_s[t+64]) + (red_s[t+128] + red_s[t+192]);
            double qq = (red_q[t] + red_q[t+64]) + (red_q[t+128] + red_q[t+192]);
            const double cnt = (double)NCOLS;
            double m = ss / cnt;
            double v = qq / cnt - m*m;
            if (v < 0.0) v = 0.0;
            double a = (double)g2[t] / sqrt(v + 1e-3);
            a2s[t] = (float)a;
            d2s[t] = (float)((double)be2[t] - a*m);
        }
        if (t < 128) { ssum[t] = 0.f; ssq[t] = 0.f; }
        __syncthreads();
    }

    {   // stage A: 1152 uint4 from padded fp16 W3
        const uint4* src = (const uint4*)g_W3Hp;
        uint4* dst = (uint4*)Asm;
        for (int idx = t; idx < (C3*WPAD)/8; idx += 256)
            dst[idx] = __ldg(&src[idx]);
    }
    {   // stage B: bn2+relu from fp16 y2, repack fp16 into padded rows
        const uint4* y2p = (const uint4*)(g_y2h + (size_t)p*(C2*SL));
        #pragma unroll
        for (int k = 0; k < 2; k++) {
            int idx = k*256 + t;              // 0..511
            int i  = idx >> 3;                // channel row
            int ch = idx & 7;                 // 16B chunk
            float a = a2s[i], d = d2s[i];
            uint4 pk = __ldg(&y2p[idx]);
            float2 f0 = __half22float2(*(__half2*)&pk.x);
            float2 f1 = __half22float2(*(__half2*)&pk.y);
            float2 f2 = __half22float2(*(__half2*)&pk.z);
            float2 f3 = __half22float2(*(__half2*)&pk.w);
            __half2 h0 = __floats2half2_rn(fmaxf(fmaf(a, f0.x, d), 0.f),
                                           fmaxf(fmaf(a, f0.y, d), 0.f));
            __half2 h1 = __floats2half2_rn(fmaxf(fmaf(a, f1.x, d), 0.f),
                                           fmaxf(fmaf(a, f1.y, d), 0.f));
            __half2 h2 = __floats2half2_rn(fmaxf(fmaf(a, f2.x, d), 0.f),
                                           fmaxf(fmaf(a, f2.y, d), 0.f));
            __half2 h3 = __floats2half2_rn(fmaxf(fmaf(a, f3.x, d), 0.f),
                                           fmaxf(fmaf(a, f3.y, d), 0.f));
            uint4 o;
            o.x = *(unsigned int*)&h0; o.y = *(unsigned int*)&h1;
            o.z = *(unsigned int*)&h2; o.w = *(unsigned int*)&h3;
            *(uint4*)(Bsm + i*WPAD + ch*8) = o;
        }
    }
    __syncthreads();

    // A fragments: 4 k-steps, held in registers
    const int m0 = wid * 16;
    unsigned af[4][4];
    {
        int g = lane >> 3, r = lane & 7;
        int row  = m0 + (g & 1)*8 + r;
        int colb = (g >> 1)*8;
        #pragma unroll
        for (int ks = 0; ks < 4; ks++) {
            unsigned addr = smem_u32(Asm + row*WPAD + ks*16 + colb);
            asm volatile("ldmatrix.sync.aligned.m8n8.x4.shared.b16 {%0,%1,%2,%3}, [%4];"
                : "=r"(af[ks][0]), "=r"(af[ks][1]), "=r"(af[ks][2]), "=r"(af[ks][3])
                : "r"(addr));
        }
    }

    float acc[8][4];
    #pragma unroll
    for (int nt = 0; nt < 8; nt++)
        #pragma unroll
        for (int j = 0; j < 4; j++) acc[nt][j] = 0.f;

    #pragma unroll
    for (int nt = 0; nt < 8; nt++) {
        #pragma unroll
        for (int ks = 0; ks < 4; ks++) {
            unsigned baddr = smem_u32(Bsm + (ks*16 + (lane & 15))*WPAD + nt*8);
            unsigned b0, b1;
            asm volatile("ldmatrix.sync.aligned.m8n8.x2.trans.shared.b16 {%0,%1}, [%2];"
                : "=r"(b0), "=r"(b1) : "r"(baddr));
            asm volatile("mma.sync.aligned.m16n8k16.row.col.f32.f16.f16.f32 "
                "{%0,%1,%2,%3},{%4,%5,%6,%7},{%8,%9},{%0,%1,%2,%3};"
                : "+f"(acc[nt][0]), "+f"(acc[nt][1]), "+f"(acc[nt][2]), "+f"(acc[nt][3])
                : "r"(af[ks][0]), "r"(af[ks][1]), "r"(af[ks][2]), "r"(af[ks][3]),
                  "r"(b0), "r"(b1));
        }
    }

    // epilogue: +b3, BN3 stats (pre-rounding), fp16 store
    {
        const int c_lo = m0 + (lane >> 2);
        const int c_hi = c_lo + 8;
        const float blo = b3[c_lo], bhi = b3[c_hi];
        float sum_lo = 0.f, sq_lo = 0.f, sum_hi = 0.f, sq_hi = 0.f;
        __half* ybase = g_y3h + (size_t)p*(C3*SL);
        #pragma unroll
        for (int nt = 0; nt < 8; nt++) {
            int s0 = nt*8 + (lane & 3)*2;
            float v0 = acc[nt][0] + blo, v1 = acc[nt][1] + blo;
            float v2 = acc[nt][2] + bhi, v3 = acc[nt][3] + bhi;
            sum_lo += v0 + v1; sq_lo = fmaf(v0, v0, fmaf(v1, v1, sq_lo));
            sum_hi += v2 + v3; sq_hi = fmaf(v2, v2, fmaf(v3, v3, sq_hi));
            __half2 hlo = __floats2half2_rn(v0, v1);
            __half2 hhi = __floats2half2_rn(v2, v3);
            *(__half2*)(ybase + c_lo*64 + s0) = hlo;
            *(__half2*)(ybase + c_hi*64 + s0) = hhi;
        }
        atomicAdd(&ssum[c_lo], sum_lo); atomicAdd(&ssq[c_lo], sq_lo);
        atomicAdd(&ssum[c_hi], sum_hi); atomicAdd(&ssq[c_hi], sq_hi);
    }
    __syncthreads();

    if (t < C3) {
        int r = blockIdx.x & (NSTRIPE-1);
        atomicAdd(&g_s3[r][t], (double)ssum[t]);
        atomicAdd(&g_q3[r][t], (double)ssq[t]);
    }
}

__global__ void fin3_kernel(const float* __restrict__ g3, const float* __restrict__ be3) {
    int c = threadIdx.x;   // 128
    double s = 0.0, q = 0.0;
    for (int r = 0; r < NSTRIPE; r++) { s += g_s3[r][c]; q += g_q3[r][c]; }
    const double cnt = (double)NCOLS;
    double m = s / cnt;
    double v = q / cnt - m*m;
    if (v < 0.0) v = 0.0;
    double a = (double)g3[c] / sqrt(v + 1e-3);
    g_a3[c] = (float)a;
    g_d3[c] = (float)((double)be3[c] - a*m);
}

// --------------------------- max over channels, softmax over slots, fuse ---
__global__ __launch_bounds__(256) void fuse_kernel(const float* __restrict__ p1,
                                                   float* __restrict__ out) {
    __shared__ float pm[8][SL];
    __shared__ float sc[SL];
    __shared__ float ex[SL];
    __shared__ float rx[SL], ry[SL], rz[SL];

    const int t = threadIdx.x;
    const int p = blockIdx.x;
    const int s2 = t & 31, cg = t >> 5;

    const __half2* y3h2 = (const __half2*)(g_y3h + (size_t)p*(C3*SL));
    float m0 = -INFINITY, m1 = -INFINITY;
    #pragma unroll 4
    for (int ci = 0; ci < 16; ci++) {
        int c = cg*16 + ci;
        float a = g_a3[c], d = g_d3[c];
        float2 f = __half22float2(y3h2[c*32 + s2]);
        m0 = fmaxf(m0, fmaf(a, f.x, d));
        m1 = fmaxf(m1, fmaf(a, f.y, d));
    }
    pm[cg][2*s2]   = m0;
    pm[cg][2*s2+1] = m1;
    __syncthreads();

    if (t < SL) {
        float mm = pm[0][t];
        #pragma unroll
        for (int g = 1; g < 8; g++) mm = fmaxf(mm, pm[g][t]);
        sc[t] = fmaxf(mm, 0.f);
    }
    __syncthreads();

    if (t < SL) {
        float mx = sc[0];
        #pragma unroll 8
        for (int i = 1; i < SL; i++) mx = fmaxf(mx, sc[i]);
        ex[t] = expf(sc[t] - mx);
    }
    __syncthreads();

    if (t < SL) {
        float ssum = 0.f;
        #pragma unroll 8
        for (int i = 0; i < SL; i++) ssum += ex[i];
        float w = ex[t] / ssum;
        float4 f = ((const float4*)g_feats)[(size_t)p*SL + t];
        rx[t] = w*f.x; ry[t] = w*f.y; rz[t] = w*f.z;
    }
    __syncthreads();

    for (int off = 32; off >= 1; off >>= 1) {
        if (t < off) { rx[t] += rx[t+off]; ry[t] += ry[t+off]; rz[t] += rz[t+off]; }
        __syncthreads();
    }

    if (t == 0) {
        const int b = p >> 12, n = p & (NPN-1);
        const float* q = p1 + (size_t)b*3*NPN;
        out[(size_t)b*3*NPN + n]          = q[n]        + rx[0];
        out[(size_t)b*3*NPN + NPN + n]    = q[NPN+n]    + ry[0];
        out[(size_t)b*3*NPN + 2*NPN + n]  = q[2*NPN+n]  + rz[0];
    }
}

// --------------------------------------------------------------------------
extern "C" void kernel_launch(void* const* d_in, const int* in_sizes, int n_in,
                              void* d_out, int out_size) {
    const float* points1 = (const float*)d_in[0];
    const float* points2 = (const float*)d_in[1];
    const float* W1  = (const float*)d_in[4];
    const float* b1  = (const float*)d_in[5];
    const float* g1  = (const float*)d_in[6];
    const float* be1 = (const float*)d_in[7];
    const float* W2  = (const float*)d_in[8];
    const float* b2  = (const float*)d_in[9];
    const float* g2  = (const float*)d_in[10];
    const float* be2 = (const float*)d_in[11];
    const float* W3  = (const float*)d_in[12];
    const float* b3  = (const float*)d_in[13];
    const float* g3  = (const float*)d_in[14];
    const float* be3 = (const float*)d_in[15];
    float* out = (float*)d_out;

    cudaFuncSetAttribute(layer2_kernel,
                         cudaFuncAttributeMaxDynamicSharedMemorySize, (int)L2_SMEM);

    knn_kernel<<<BB*NPN*2, 128>>>(points1, points2);                 // 1
    stats1_kernel<<<2048, 256>>>(W1, b1, W2, W3);                    // 2
    layer2_kernel<<<NPTS/4, 256, L2_SMEM>>>(W1, b1, g1, be1, b2);    // 3
    layer3_kernel<<<NPTS, 256>>>(b3, g2, be2);                       // 4 -> ncu
    fin3_kernel<<<1, C3>>>(g3, be3);                                 // 5
    fuse_kernel<<<NPTS, 256>>>(points1, out);                        // 6
}

// round 15
// speedup vs baseline: 2.0008x; 1.1777x over previous
#include <cuda_runtime.h>
#include <cuda_fp16.h>
#include <math.h>

#define BB    4
#define NPN   4096          // points per batch
#define KNBR  32            // k
#define SL    64            // 2k slots
#define C1    64
#define C2    64
#define C3    128
#define NPTS  (BB*NPN)      // 16384
#define NCOLS (NPTS*SL)     // 1,048,576
#define NSTRIPE 32
#define WPAD  72            // padded row stride (halves) for ldmatrix tiles
#define PTS3  4             // points per layer3 block

// packed f32x2 FMA: acc = a*b + acc (two fp32 lanes per instruction)
#define FMA2(acc, a, b) \
    asm("fma.rn.f32x2 %0, %1, %2, %0;" : "+l"(acc) : "l"(a), "l"(b))

__device__ __forceinline__ unsigned long long pack_dup(float w) {
    unsigned long long r;
    asm("mov.b64 %0, {%1, %1};" : "=l"(r) : "f"(w));
    return r;
}
__device__ __forceinline__ void unpack2(unsigned long long v, float& lo, float& hi) {
    asm("mov.b64 {%0, %1}, %2;" : "=f"(lo), "=f"(hi) : "l"(v));
}
__device__ __forceinline__ unsigned int smem_u32(const void* p) {
    unsigned int a;
    asm("{ .reg .u64 t; cvta.to.shared.u64 t, %1; cvt.u32.u64 %0, t; }"
        : "=r"(a) : "l"(p));
    return a;
}

// ---------------- scratch (static device memory; no runtime allocation) ----
__device__ float  g_feats[(size_t)NCOLS*4];  // [point][slot][4] = resi.xyz, dist
__device__ __half g_y2h [(size_t)NCOLS*C2];  // [point][c][s] fp16
__device__ __half g_y3h [(size_t)NCOLS*C3];  // [point][c][s] fp16
__device__ float  g_W2T [C1*C2];             // [i][c]
__device__ __align__(16) __half g_W3Hp[C3*WPAD];  // W3 fp16, padded rows

__device__ double g_s1[C1], g_q1[C1];
__device__ double g_s2[NSTRIPE][C2], g_q2[NSTRIPE][C2];
__device__ double g_s3[NSTRIPE][C3], g_q3[NSTRIPE][C3];
__device__ float  g_a3[C3], g_d3[C3];

// ------------------------------------------------------------------- KNN
__device__ __forceinline__ unsigned int f2u_ordered(float f) {
    unsigned int u = __float_as_uint(f);
    return (u & 0x80000000u) ? ~u : (u | 0x80000000u);
}

__global__ __launch_bounds__(128) void knn_kernel(const float* __restrict__ p1,
                                                  const float* __restrict__ p2) {
    __shared__ __align__(16) unsigned int keys[NPN];
    __shared__ unsigned int hist[256];
    __shared__ unsigned int sel[KNBR];
    __shared__ unsigned int ties[40];
    __shared__ unsigned int s_cnt, s_tcnt, s_pref, s_kk;

    const int t   = threadIdx.x;
    const unsigned int bid = blockIdx.x;
    const int set = bid & 1;
    const int pq  = bid >> 1;
    const int b   = pq >> 12;
    const int n   = pq & (NPN-1);

    if (bid == 0) {   // fold stats zeroing into block 0
        for (int i = t; i < C1; i += 128) { g_s1[i] = 0.0; g_q1[i] = 0.0; }
        double* s2 = &g_s2[0][0]; double* q2 = &g_q2[0][0];
        for (int i = t; i < NSTRIPE*C2; i += 128) { s2[i] = 0.0; q2[i] = 0.0; }
        double* s3 = &g_s3[0][0]; double* q3 = &g_q3[0][0];
        for (int i = t; i < NSTRIPE*C3; i += 128) { s3[i] = 0.0; q3[i] = 0.0; }
    }

    const float* qb  = p1 + (size_t)b*3*NPN;
    const float* tgt = (set ? p2 : p1) + (size_t)b*3*NPN;

    const float qx = qb[n], qy = qb[NPN+n], qz = qb[2*NPN+n];
    const float qn = qx*qx + qy*qy + qz*qz;

    hist[t] = 0u; hist[t+128] = 0u;
    if (t == 0) { s_pref = 0u; s_kk = KNBR; s_cnt = 0u; s_tcnt = 0u; }
    __syncthreads();

    {
        const float4* tx4 = (const float4*)tgt;
        const float4* ty4 = (const float4*)(tgt + NPN);
        const float4* tz4 = (const float4*)(tgt + 2*NPN);
        uint4* keys4 = (uint4*)keys;
        #pragma unroll
        for (int k = 0; k < 8; k++) {
            int q = k*128 + t;
            float4 X = tx4[q], Y = ty4[q], Z = tz4[q];
            uint4 kv;
            { float tn = X.x*X.x + Y.x*Y.x + Z.x*Z.x;
              float dt = qx*X.x + qy*Y.x + qz*Z.x;
              kv.x = f2u_ordered(qn + tn - 2.0f*dt); }
            { float tn = X.y*X.y + Y.y*Y.y + Z.y*Z.y;
              float dt = qx*X.y + qy*Y.y + qz*Z.y;
              kv.y = f2u_ordered(qn + tn - 2.0f*dt); }
            { float tn = X.z*X.z + Y.z*Y.z + Z.z*Z.z;
              float dt = qx*X.z + qy*Y.z + qz*Z.z;
              kv.z = f2u_ordered(qn + tn - 2.0f*dt); }
            { float tn = X.w*X.w + Y.w*Y.w + Z.w*Z.w;
              float dt = qx*X.w + qy*Y.w + qz*Z.w;
              kv.w = f2u_ordered(qn + tn - 2.0f*dt); }
            keys4[q] = kv;
            atomicAdd(&hist[kv.x >> 24], 1u);
            atomicAdd(&hist[kv.y >> 24], 1u);
            atomicAdd(&hist[kv.z >> 24], 1u);
            atomicAdd(&hist[kv.w >> 24], 1u);
        }
    }
    __syncthreads();

    #pragma unroll
    for (int pass = 0; pass < 4; pass++) {
        const int shift = 24 - pass*8;
        const unsigned int pref = s_pref;
        const unsigned int kk   = s_kk;
        if (t < 32) {
            const int base = t * 8;
            unsigned int vals[8];
            unsigned int s = 0;
            #pragma unroll
            for (int j = 0; j < 8; j++) { s += hist[base+j]; vals[j] = s; }
            unsigned int tot = s;
            #pragma unroll
            for (int off = 1; off < 32; off <<= 1) {
                unsigned int nb = __shfl_up_sync(0xffffffffu, tot, off);
                if (t >= off) tot += nb;
            }
            const unsigned int offset = tot - s;
            #pragma unroll
            for (int j = 0; j < 8; j++) hist[base+j] = vals[j] + offset;
        }
        __syncthreads();
        #pragma unroll
        for (int r = 0; r < 2; r++) {
            int bin = t + r*128;
            unsigned int cum  = hist[bin];
            unsigned int prev = bin ? hist[bin-1] : 0u;
            if (cum >= kk && prev < kk) {
                s_pref = pref | ((unsigned int)bin << shift);
                s_kk   = kk - prev;
            }
        }
        __syncthreads();
        if (pass < 3) {
            const unsigned int npref = s_pref;
            hist[t] = 0u; hist[t+128] = 0u;
            __syncthreads();
            const int nshift = shift - 8;
            const unsigned int nmask = 0xFFFFFFFFu << (nshift + 8);
            const uint4* keys4 = (const uint4*)keys;
            #pragma unroll
            for (int k = 0; k < 8; k++) {
                uint4 kv = keys4[k*128 + t];
                if ((kv.x & nmask) == npref) atomicAdd(&hist[(kv.x >> nshift) & 255u], 1u);
                if ((kv.y & nmask) == npref) atomicAdd(&hist[(kv.y >> nshift) & 255u], 1u);
                if ((kv.z & nmask) == npref) atomicAdd(&hist[(kv.z >> nshift) & 255u], 1u);
                if ((kv.w & nmask) == npref) atomicAdd(&hist[(kv.w >> nshift) & 255u], 1u);
            }
            __syncthreads();
        }
    }

    const unsigned int T = s_pref;
    {
        const uint4* keys4 = (const uint4*)keys;
        #pragma unroll
        for (int k = 0; k < 8; k++) {
            int q = k*128 + t;
            uint4 kv = keys4[q];
            unsigned int j0 = (unsigned)(q*4);
            #pragma unroll
            for (int m = 0; m < 4; m++) {
                unsigned int key = (m==0)?kv.x:(m==1)?kv.y:(m==2)?kv.z:kv.w;
                if (key < T) {
                    unsigned int pos = atomicAdd(&s_cnt, 1u);
                    if (pos < KNBR) sel[pos] = j0 + m;
                } else if (key == T) {
                    unsigned int tp = atomicAdd(&s_tcnt, 1u);
                    if (tp < 40u) ties[tp] = j0 + m;
                }
            }
        }
    }
    __syncthreads();

    if (t == 0) {
        unsigned int cnt = s_cnt, kk = s_kk, tc = s_tcnt;
        if (cnt > KNBR) cnt = KNBR;
        if (kk > KNBR - cnt) kk = KNBR - cnt;
        if (tc <= 40u) {
            for (unsigned int m = 0; m < kk; m++) {
                unsigned int best = 0xFFFFFFFFu, bi = m;
                for (unsigned int r = m; r < tc; r++)
                    if (ties[r] < best) { best = ties[r]; bi = r; }
                ties[bi] = ties[m]; ties[m] = best;
                sel[cnt + m] = best;
            }
        } else {
            unsigned int filled = 0;
            for (int j = 0; j < NPN && filled < kk; j++)
                if (keys[j] == T) { sel[cnt + filled] = (unsigned int)j; filled++; }
        }
    }
    __syncthreads();

    if (t < KNBR) {
        int j = (int)sel[t];
        float tx = tgt[j], ty = tgt[NPN+j], tz = tgt[2*NPN+j];
        float rx = tx - qx, ry = ty - qy, rz = tz - qz;
        float dist = sqrtf(rx*rx + ry*ry + rz*rz);
        float4* out4 = (float4*)g_feats;
        out4[(size_t)pq*SL + set*KNBR + t] = make_float4(rx, ry, rz, dist);
    }
}

// --------- layer-1 BN statistics (+ W2T / padded fp16 W3 in block 0) -------
__global__ __launch_bounds__(256) void stats1_kernel(const float* __restrict__ W1,
                                                     const float* __restrict__ b1,
                                                     const float* __restrict__ W2,
                                                     const float* __restrict__ W3) {
    __shared__ float w1s[C1*4];
    __shared__ float b1s[C1];
    __shared__ float ssum[C1], ssq[C1];
    const int t = threadIdx.x;

    if (blockIdx.x == 0) {
        for (int idx = t; idx < C2*C1; idx += 256) {
            int c = idx >> 6, i = idx & 63;
            g_W2T[i*C2 + c] = W2[idx];
        }
        for (int idx = t; idx < C3*C2; idx += 256) {
            int m = idx >> 6, k = idx & 63;
            g_W3Hp[m*WPAD + k] = __float2half_rn(W3[idx]);
        }
    }

    if (t < C1*4) w1s[t] = W1[t];
    if (t < C1)  { b1s[t] = b1[t]; ssum[t] = 0.f; ssq[t] = 0.f; }
    __syncthreads();

    const int c = t & 63, g = t >> 6;
    const int COLS_PER_BLOCK = NCOLS / 2048;
    const int col0 = blockIdx.x * COLS_PER_BLOCK;
    const float w0 = w1s[c*4+0], w1 = w1s[c*4+1], w2 = w1s[c*4+2], w3 = w1s[c*4+3];
    const float bc = b1s[c];
    float sum = 0.f, sq = 0.f;
    const float4* f4 = (const float4*)g_feats;
    for (int col = col0 + g; col < col0 + COLS_PER_BLOCK; col += 4) {
        float4 f = f4[col];
        float y = fmaf(w0, f.x, fmaf(w1, f.y, fmaf(w2, f.z, fmaf(w3, f.w, bc))));
        sum += y; sq = fmaf(y, y, sq);
    }
    atomicAdd(&ssum[c], sum);
    atomicAdd(&ssq[c],  sq);
    __syncthreads();
    if (t < C1) {
        atomicAdd(&g_s1[t], (double)ssum[t]);
        atomicAdd(&g_q1[t], (double)ssq[t]);
    }
}

// ------------------------------------ layer2: x2=relu(bn1(y1)), y2=W2 x2+b2
#define L2_XS    0
#define L2_FSH   (L2_XS + 4*4096)
#define L2_W1    (L2_FSH + 1024)
#define L2_B1    (L2_W1 + 256)
#define L2_A1    (L2_B1 + 64)
#define L2_D1    (L2_A1 + 64)
#define L2_SSUM  (L2_D1 + 64)
#define L2_SSQ   (L2_SSUM + 64)
#define L2_SMEM  ((L2_SSQ + 64) * sizeof(float))

__global__ __launch_bounds__(256, 2) void layer2_kernel(const float* __restrict__ W1,
                                                        const float* __restrict__ b1,
                                                        const float* __restrict__ g1,
                                                        const float* __restrict__ be1,
                                                        const float* __restrict__ b2) {
    extern __shared__ __align__(16) float sm[];
    float* xs   = sm + L2_XS;
    float* fsh  = sm + L2_FSH;
    float* w1s  = sm + L2_W1;
    float* b1s  = sm + L2_B1;
    float* a1s  = sm + L2_A1;
    float* d1s  = sm + L2_D1;
    float* ssum = sm + L2_SSUM;
    float* ssq  = sm + L2_SSQ;

    const int t  = threadIdx.x;
    const int p0 = blockIdx.x * 4;

    w1s[t] = W1[t];
    if (t < 64) {
        b1s[t] = b1[t]; ssum[t] = 0.f; ssq[t] = 0.f;
        const double cnt = (double)NCOLS;
        double m = g_s1[t] / cnt;
        double v = g_q1[t] / cnt - m*m;
        if (v < 0.0) v = 0.0;
        double a = (double)g1[t] / sqrt(v + 1e-3);
        a1s[t] = (float)a;
        d1s[t] = (float)((double)be1[t] - a*m);
    }
    ((float4*)fsh)[t] = ((const float4*)g_feats)[(size_t)p0*SL + t];
    __syncthreads();

    {
        const float4* fsh4 = (const float4*)fsh;
        #pragma unroll 4
        for (int k = 0; k < 64; k++) {
            int idx = k*256 + t;
            int pt = idx >> 12;
            int i  = (idx >> 6) & 63;
            int s  = idx & 63;
            float4 f = fsh4[pt*SL + s];
            float y = fmaf(w1s[i*4+0], f.x, fmaf(w1s[i*4+1], f.y,
                      fmaf(w1s[i*4+2], f.z, fmaf(w1s[i*4+3], f.w, b1s[i]))));
            xs[pt*4096 + i*64 + s] = fmaxf(fmaf(a1s[i], y, d1s[i]), 0.f);
        }
    }
    __syncthreads();

    const int pt = t >> 6, wt_tid = t & 63;
    const int cq = wt_tid & 15, sg = wt_tid >> 4;
    const float* xp = xs + pt*4096 + sg*16;
    const float4* wrow = ((const float4*)g_W2T) + cq;

    unsigned long long acc[32];
    #pragma unroll
    for (int j = 0; j < 32; j++) acc[j] = 0ull;

    float4 wv = __ldg(wrow);
    ulonglong2 u0, u1, u2, u3;
    { const ulonglong2* xr = (const ulonglong2*)xp;
      u0 = xr[0]; u1 = xr[1]; u2 = xr[2]; u3 = xr[3]; }

    #pragma unroll 2
    for (int i = 0; i < C1; i++) {
        const int inext = (i < C1-1) ? i+1 : i;
        float4 wn = __ldg(wrow + inext*16);
        const ulonglong2* xn = (const ulonglong2*)(xp + inext*64);
        ulonglong2 n0 = xn[0], n1 = xn[1], n2 = xn[2], n3 = xn[3];

        unsigned long long w0 = pack_dup(wv.x), w1 = pack_dup(wv.y);
        unsigned long long w2 = pack_dup(wv.z), w3 = pack_dup(wv.w);
        FMA2(acc[ 0], w0, u0.x); FMA2(acc[ 1], w0, u0.y);
        FMA2(acc[ 2], w0, u1.x); FMA2(acc[ 3], w0, u1.y);
        FMA2(acc[ 4], w0, u2.x); FMA2(acc[ 5], w0, u2.y);
        FMA2(acc[ 6], w0, u3.x); FMA2(acc[ 7], w0, u3.y);
        FMA2(acc[ 8], w1, u0.x); FMA2(acc[ 9], w1, u0.y);
        FMA2(acc[10], w1, u1.x); FMA2(acc[11], w1, u1.y);
        FMA2(acc[12], w1, u2.x); FMA2(acc[13], w1, u2.y);
        FMA2(acc[14], w1, u3.x); FMA2(acc[15], w1, u3.y);
        FMA2(acc[16], w2, u0.x); FMA2(acc[17], w2, u0.y);
        FMA2(acc[18], w2, u1.x); FMA2(acc[19], w2, u1.y);
        FMA2(acc[20], w2, u2.x); FMA2(acc[21], w2, u2.y);
        FMA2(acc[22], w2, u3.x); FMA2(acc[23], w2, u3.y);
        FMA2(acc[24], w3, u0.x); FMA2(acc[25], w3, u0.y);
        FMA2(acc[26], w3, u1.x); FMA2(acc[27], w3, u1.y);
        FMA2(acc[28], w3, u2.x); FMA2(acc[29], w3, u2.y);
        FMA2(acc[30], w3, u3.x); FMA2(acc[31], w3, u3.y);

        wv = wn; u0 = n0; u1 = n1; u2 = n2; u3 = n3;
    }

    __half* ybase = g_y2h + (size_t)(p0 + pt)*(C2*SL) + sg*16;
    #pragma unroll
    for (int cc = 0; cc < 4; cc++) {
        const int c = cq*4 + cc;
        const float bc = b2[c];
        float v[16];
        #pragma unroll
        for (int sp = 0; sp < 8; sp++)
            unpack2(acc[cc*8 + sp], v[2*sp], v[2*sp+1]);
        float csum = 0.f, csq = 0.f;
        #pragma unroll
        for (int j = 0; j < 16; j++) {
            v[j] += bc; csum += v[j]; csq = fmaf(v[j], v[j], csq);
        }
        uint4 pk0, pk1;
        __half2 h;
        h = __floats2half2_rn(v[0],  v[1]);  pk0.x = *(unsigned int*)&h;
        h = __floats2half2_rn(v[2],  v[3]);  pk0.y = *(unsigned int*)&h;
        h = __floats2half2_rn(v[4],  v[5]);  pk0.z = *(unsigned int*)&h;
        h = __floats2half2_rn(v[6],  v[7]);  pk0.w = *(unsigned int*)&h;
        h = __floats2half2_rn(v[8],  v[9]);  pk1.x = *(unsigned int*)&h;
        h = __floats2half2_rn(v[10], v[11]); pk1.y = *(unsigned int*)&h;
        h = __floats2half2_rn(v[12], v[13]); pk1.z = *(unsigned int*)&h;
        h = __floats2half2_rn(v[14], v[15]); pk1.w = *(unsigned int*)&h;
        uint4* o = (uint4*)(ybase + c*64);
        o[0] = pk0; o[1] = pk1;
        atomicAdd(&ssum[c], csum);
        atomicAdd(&ssq[c],  csq);
    }
    __syncthreads();
    if (t < C2) {
        int r = blockIdx.x & (NSTRIPE-1);
        atomicAdd(&g_s2[r][t], (double)ssum[t]);
        atomicAdd(&g_q2[r][t], (double)ssq[t]);
    }
}

// ---------------- layer3 via mma.sync (HMMA), 4 pts/block -------------------
// 8 warps; warp w owns m-rows 16w..16w+15. A staged + frags loaded ONCE,
// reused across PTS3 points. BN3 stats accumulated in smem across points.
__global__ __launch_bounds__(256) void layer3_kernel(const float* __restrict__ b3,
                                                     const float* __restrict__ g2,
                                                     const float* __restrict__ be2) {
    __shared__ __align__(16) __half Asm[C3*WPAD];        // 18432 B
    __shared__ __align__(16) __half Bsm[PTS3][C2*WPAD];  // 4 x 9216 B
    __shared__ float a2s[C2], d2s[C2];
    __shared__ float ssum[C3], ssq[C3];

    const int t    = threadIdx.x;
    const int wid  = t >> 5;
    const int lane = t & 31;
    const int p0   = blockIdx.x * PTS3;

    {   // parallel BN2 finalize (reduction buffers aliased into Asm)
        double* red_s = (double*)Asm;
        double* red_q = ((double*)Asm) + 256;
        const int ch = t & 63, grp = t >> 6;
        double s = 0.0, q = 0.0;
        #pragma unroll
        for (int r = 0; r < 8; r++) {
            s += g_s2[grp*8 + r][ch];
            q += g_q2[grp*8 + r][ch];
        }
        red_s[t] = s; red_q[t] = q;
        __syncthreads();
        if (t < 64) {
            double ss = (red_s[t] + red_s[t+64]) + (red_s[t+128] + red_s[t+192]);
            double qq = (red_q[t] + red_q[t+64]) + (red_q[t+128] + red_q[t+192]);
            const double cnt = (double)NCOLS;
            double m = ss / cnt;
            double v = qq / cnt - m*m;
            if (v < 0.0) v = 0.0;
            double a = (double)g2[t] / sqrt(v + 1e-3);
            a2s[t] = (float)a;
            d2s[t] = (float)((double)be2[t] - a*m);
        }
        if (t < 128) { ssum[t] = 0.f; ssq[t] = 0.f; }
        __syncthreads();
    }

    {   // stage A: 1152 uint4 from padded fp16 W3
        const uint4* src = (const uint4*)g_W3Hp;
        uint4* dst = (uint4*)Asm;
        for (int idx = t; idx < (C3*WPAD)/8; idx += 256)
            dst[idx] = __ldg(&src[idx]);
    }
    {   // stage B for all PTS3 points: bn2+relu, repack fp16, padded rows
        const uint4* y2p = (const uint4*)(g_y2h + (size_t)p0*(C2*SL));
        #pragma unroll
        for (int k = 0; k < 2*PTS3; k++) {
            int idx = k*256 + t;              // 0..2047
            int pt = idx >> 9;
            int w  = idx & 511;
            int i  = w >> 3;
            int ch = w & 7;
            float a = a2s[i], d = d2s[i];
            uint4 pk = __ldg(&y2p[idx]);
            float2 f0 = __half22float2(*(__half2*)&pk.x);
            float2 f1 = __half22float2(*(__half2*)&pk.y);
            float2 f2 = __half22float2(*(__half2*)&pk.z);
            float2 f3 = __half22float2(*(__half2*)&pk.w);
            __half2 h0 = __floats2half2_rn(fmaxf(fmaf(a, f0.x, d), 0.f),
                                           fmaxf(fmaf(a, f0.y, d), 0.f));
            __half2 h1 = __floats2half2_rn(fmaxf(fmaf(a, f1.x, d), 0.f),
                                           fmaxf(fmaf(a, f1.y, d), 0.f));
            __half2 h2 = __floats2half2_rn(fmaxf(fmaf(a, f2.x, d), 0.f),
                                           fmaxf(fmaf(a, f2.y, d), 0.f));
            __half2 h3 = __floats2half2_rn(fmaxf(fmaf(a, f3.x, d), 0.f),
                                           fmaxf(fmaf(a, f3.y, d), 0.f));
            uint4 o;
            o.x = *(unsigned int*)&h0; o.y = *(unsigned int*)&h1;
            o.z = *(unsigned int*)&h2; o.w = *(unsigned int*)&h3;
            *(uint4*)(&Bsm[pt][i*WPAD + ch*8]) = o;
        }
    }
    __syncthreads();

    // A fragments loaded once, reused for all points
    const int m0 = wid * 16;
    unsigned af[4][4];
    {
        int g = lane >> 3, r = lane & 7;
        int row  = m0 + (g & 1)*8 + r;
        int colb = (g >> 1)*8;
        #pragma unroll
        for (int ks = 0; ks < 4; ks++) {
            unsigned addr = smem_u32(Asm + row*WPAD + ks*16 + colb);
            asm volatile("ldmatrix.sync.aligned.m8n8.x4.shared.b16 {%0,%1,%2,%3}, [%4];"
                : "=r"(af[ks][0]), "=r"(af[ks][1]), "=r"(af[ks][2]), "=r"(af[ks][3])
                : "r"(addr));
        }
    }

    const int c_lo = m0 + (lane >> 2);
    const int c_hi = c_lo + 8;
    const float blo = b3[c_lo], bhi = b3[c_hi];
    float sum_lo = 0.f, sq_lo = 0.f, sum_hi = 0.f, sq_hi = 0.f;

    #pragma unroll
    for (int pt = 0; pt < PTS3; pt++) {
        float acc[8][4];
        #pragma unroll
        for (int nt = 0; nt < 8; nt++)
            #pragma unroll
            for (int j = 0; j < 4; j++) acc[nt][j] = 0.f;

        #pragma unroll
        for (int nt = 0; nt < 8; nt++) {
            #pragma unroll
            for (int ks = 0; ks < 4; ks++) {
                unsigned baddr = smem_u32(&Bsm[pt][(ks*16 + (lane & 15))*WPAD + nt*8]);
                unsigned b0, b1;
                asm volatile("ldmatrix.sync.aligned.m8n8.x2.trans.shared.b16 {%0,%1}, [%2];"
                    : "=r"(b0), "=r"(b1) : "r"(baddr));
                asm volatile("mma.sync.aligned.m16n8k16.row.col.f32.f16.f16.f32 "
                    "{%0,%1,%2,%3},{%4,%5,%6,%7},{%8,%9},{%0,%1,%2,%3};"
                    : "+f"(acc[nt][0]), "+f"(acc[nt][1]), "+f"(acc[nt][2]), "+f"(acc[nt][3])
                    : "r"(af[ks][0]), "r"(af[ks][1]), "r"(af[ks][2]), "r"(af[ks][3]),
                      "r"(b0), "r"(b1));
            }
        }

        __half* ybase = g_y3h + (size_t)(p0 + pt)*(C3*SL);
        #pragma unroll
        for (int nt = 0; nt < 8; nt++) {
            int s0 = nt*8 + (lane & 3)*2;
            float v0 = acc[nt][0] + blo, v1 = acc[nt][1] + blo;
            float v2 = acc[nt][2] + bhi, v3 = acc[nt][3] + bhi;
            sum_lo += v0 + v1; sq_lo = fmaf(v0, v0, fmaf(v1, v1, sq_lo));
            sum_hi += v2 + v3; sq_hi = fmaf(v2, v2, fmaf(v3, v3, sq_hi));
            __half2 hlo = __floats2half2_rn(v0, v1);
            __half2 hhi = __floats2half2_rn(v2, v3);
            *(__half2*)(ybase + c_lo*64 + s0) = hlo;
            *(__half2*)(ybase + c_hi*64 + s0) = hhi;
        }
    }

    atomicAdd(&ssum[c_lo], sum_lo); atomicAdd(&ssq[c_lo], sq_lo);
    atomicAdd(&ssum[c_hi], sum_hi); atomicAdd(&ssq[c_hi], sq_hi);
    __syncthreads();

    if (t < C3) {
        int r = blockIdx.x & (NSTRIPE-1);
        atomicAdd(&g_s3[r][t], (double)ssum[t]);
        atomicAdd(&g_q3[r][t], (double)ssq[t]);
    }
}

__global__ void fin3_kernel(const float* __restrict__ g3, const float* __restrict__ be3) {
    int c = threadIdx.x;   // 128
    double s = 0.0, q = 0.0;
    for (int r = 0; r < NSTRIPE; r++) { s += g_s3[r][c]; q += g_q3[r][c]; }
    const double cnt = (double)NCOLS;
    double m = s / cnt;
    double v = q / cnt - m*m;
    if (v < 0.0) v = 0.0;
    double a = (double)g3[c] / sqrt(v + 1e-3);
    g_a3[c] = (float)a;
    g_d3[c] = (float)((double)be3[c] - a*m);
}

// --------------------------- max over channels, softmax over slots, fuse ---
__global__ __launch_bounds__(256) void fuse_kernel(const float* __restrict__ p1,
                                                   float* __restrict__ out) {
    __shared__ float pm[8][SL];
    __shared__ float sc[SL];
    __shared__ float ex[SL];
    __shared__ float rx[SL], ry[SL], rz[SL];

    const int t = threadIdx.x;
    const int p = blockIdx.x;
    const int s2 = t & 31, cg = t >> 5;

    const __half2* y3h2 = (const __half2*)(g_y3h + (size_t)p*(C3*SL));
    float m0 = -INFINITY, m1 = -INFINITY;
    #pragma unroll 4
    for (int ci = 0; ci < 16; ci++) {
        int c = cg*16 + ci;
        float a = g_a3[c], d = g_d3[c];
        float2 f = __half22float2(y3h2[c*32 + s2]);
        m0 = fmaxf(m0, fmaf(a, f.x, d));
        m1 = fmaxf(m1, fmaf(a, f.y, d));
    }
    pm[cg][2*s2]   = m0;
    pm[cg][2*s2+1] = m1;
    __syncthreads();

    if (t < SL) {
        float mm = pm[0][t];
        #pragma unroll
        for (int g = 1; g < 8; g++) mm = fmaxf(mm, pm[g][t]);
        sc[t] = fmaxf(mm, 0.f);
    }
    __syncthreads();

    if (t < SL) {
        float mx = sc[0];
        #pragma unroll 8
        for (int i = 1; i < SL; i++) mx = fmaxf(mx, sc[i]);
        ex[t] = expf(sc[t] - mx);
    }
    __syncthreads();

    if (t < SL) {
        float ssum = 0.f;
        #pragma unroll 8
        for (int i = 0; i < SL; i++) ssum += ex[i];
        float w = ex[t] / ssum;
        float4 f = ((const float4*)g_feats)[(size_t)p*SL + t];
        rx[t] = w*f.x; ry[t] = w*f.y; rz[t] = w*f.z;
    }
    __syncthreads();

    for (int off = 32; off >= 1; off >>= 1) {
        if (t < off) { rx[t] += rx[t+off]; ry[t] += ry[t+off]; rz[t] += rz[t+off]; }
        __syncthreads();
    }

    if (t == 0) {
        const int b = p >> 12, n = p & (NPN-1);
        const float* q = p1 + (size_t)b*3*NPN;
        out[(size_t)b*3*NPN + n]          = q[n]        + rx[0];
        out[(size_t)b*3*NPN + NPN + n]    = q[NPN+n]    + ry[0];
        out[(size_t)b*3*NPN + 2*NPN + n]  = q[2*NPN+n]  + rz[0];
    }
}

// --------------------------------------------------------------------------
extern "C" void kernel_launch(void* const* d_in, const int* in_sizes, int n_in,
                              void* d_out, int out_size) {
    const float* points1 = (const float*)d_in[0];
    const float* points2 = (const float*)d_in[1];
    const float* W1  = (const float*)d_in[4];
    const float* b1  = (const float*)d_in[5];
    const float* g1  = (const float*)d_in[6];
    const float* be1 = (const float*)d_in[7];
    const float* W2  = (const float*)d_in[8];
    const float* b2  = (const float*)d_in[9];
    const float* g2  = (const float*)d_in[10];
    const float* be2 = (const float*)d_in[11];
    const float* W3  = (const float*)d_in[12];
    const float* b3  = (const float*)d_in[13];
    const float* g3  = (const float*)d_in[14];
    const float* be3 = (const float*)d_in[15];
    float* out = (float*)d_out;

    cudaFuncSetAttribute(layer2_kernel,
                         cudaFuncAttributeMaxDynamicSharedMemorySize, (int)L2_SMEM);

    knn_kernel<<<BB*NPN*2, 128>>>(points1, points2);                 // 1
    stats1_kernel<<<2048, 256>>>(W1, b1, W2, W3);                    // 2
    layer2_kernel<<<NPTS/4, 256, L2_SMEM>>>(W1, b1, g1, be1, b2);    // 3
    layer3_kernel<<<NPTS/PTS3, 256>>>(b3, g2, be2);                  // 4 -> ncu
    fin3_kernel<<<1, C3>>>(g3, be3);                                 // 5
    fuse_kernel<<<NPTS, 256>>>(points1, out);                        // 6
}

// round 16
// speedup vs baseline: 2.3747x; 1.1869x over previous
#include <cuda_runtime.h>
#include <cuda_fp16.h>
#include <math.h>

#define BB    4
#define NPN   4096          // points per batch
#define KNBR  32            // k
#define SL    64            // 2k slots
#define C1    64
#define C2    64
#define C3    128
#define NPTS  (BB*NPN)      // 16384
#define NCOLS (NPTS*SL)     // 1,048,576
#define NSTRIPE 32
#define WPAD  72            // padded row stride (halves) for ldmatrix tiles
#define PTS3  4             // points per layer3 block
#define PTS2  4             // points per layer2 block

__device__ __forceinline__ unsigned int smem_u32(const void* p) {
    unsigned int a;
    asm("{ .reg .u64 t; cvta.to.shared.u64 t, %1; cvt.u32.u64 %0, t; }"
        : "=r"(a) : "l"(p));
    return a;
}

// ---------------- scratch (static device memory; no runtime allocation) ----
__device__ float  g_feats[(size_t)NCOLS*4];  // [point][slot][4] = resi.xyz, dist
__device__ __half g_y2h [(size_t)NCOLS*C2];  // [point][c][s] fp16
__device__ __half g_y3h [(size_t)NCOLS*C3];  // [point][c][s] fp16
__device__ __align__(16) __half g_W2Hp[C2*WPAD];  // W2 fp16, padded rows
__device__ __align__(16) __half g_W3Hp[C3*WPAD];  // W3 fp16, padded rows

__device__ double g_s1[C1], g_q1[C1];
__device__ double g_s2[NSTRIPE][C2], g_q2[NSTRIPE][C2];
__device__ double g_s3[NSTRIPE][C3], g_q3[NSTRIPE][C3];
__device__ float  g_a3[C3], g_d3[C3];

// ------------------------------------------------------------------- KNN
__device__ __forceinline__ unsigned int f2u_ordered(float f) {
    unsigned int u = __float_as_uint(f);
    return (u & 0x80000000u) ? ~u : (u | 0x80000000u);
}

__global__ __launch_bounds__(128) void knn_kernel(const float* __restrict__ p1,
                                                  const float* __restrict__ p2) {
    __shared__ __align__(16) unsigned int keys[NPN];
    __shared__ unsigned int hist[256];
    __shared__ unsigned int sel[KNBR];
    __shared__ unsigned int ties[40];
    __shared__ unsigned int s_cnt, s_tcnt, s_pref, s_kk;

    const int t   = threadIdx.x;
    const unsigned int bid = blockIdx.x;
    const int set = bid & 1;
    const int pq  = bid >> 1;
    const int b   = pq >> 12;
    const int n   = pq & (NPN-1);

    if (bid == 0) {   // fold stats zeroing into block 0
        for (int i = t; i < C1; i += 128) { g_s1[i] = 0.0; g_q1[i] = 0.0; }
        double* s2 = &g_s2[0][0]; double* q2 = &g_q2[0][0];
        for (int i = t; i < NSTRIPE*C2; i += 128) { s2[i] = 0.0; q2[i] = 0.0; }
        double* s3 = &g_s3[0][0]; double* q3 = &g_q3[0][0];
        for (int i = t; i < NSTRIPE*C3; i += 128) { s3[i] = 0.0; q3[i] = 0.0; }
    }

    const float* qb  = p1 + (size_t)b*3*NPN;
    const float* tgt = (set ? p2 : p1) + (size_t)b*3*NPN;

    const float qx = qb[n], qy = qb[NPN+n], qz = qb[2*NPN+n];
    const float qn = qx*qx + qy*qy + qz*qz;

    hist[t] = 0u; hist[t+128] = 0u;
    if (t == 0) { s_pref = 0u; s_kk = KNBR; s_cnt = 0u; s_tcnt = 0u; }
    __syncthreads();

    {
        const float4* tx4 = (const float4*)tgt;
        const float4* ty4 = (const float4*)(tgt + NPN);
        const float4* tz4 = (const float4*)(tgt + 2*NPN);
        uint4* keys4 = (uint4*)keys;
        #pragma unroll
        for (int k = 0; k < 8; k++) {
            int q = k*128 + t;
            float4 X = tx4[q], Y = ty4[q], Z = tz4[q];
            uint4 kv;
            { float tn = X.x*X.x + Y.x*Y.x + Z.x*Z.x;
              float dt = qx*X.x + qy*Y.x + qz*Z.x;
              kv.x = f2u_ordered(qn + tn - 2.0f*dt); }
            { float tn = X.y*X.y + Y.y*Y.y + Z.y*Z.y;
              float dt = qx*X.y + qy*Y.y + qz*Z.y;
              kv.y = f2u_ordered(qn + tn - 2.0f*dt); }
            { float tn = X.z*X.z + Y.z*Y.z + Z.z*Z.z;
              float dt = qx*X.z + qy*Y.z + qz*Z.z;
              kv.z = f2u_ordered(qn + tn - 2.0f*dt); }
            { float tn = X.w*X.w + Y.w*Y.w + Z.w*Z.w;
              float dt = qx*X.w + qy*Y.w + qz*Z.w;
              kv.w = f2u_ordered(qn + tn - 2.0f*dt); }
            keys4[q] = kv;
            atomicAdd(&hist[kv.x >> 24], 1u);
            atomicAdd(&hist[kv.y >> 24], 1u);
            atomicAdd(&hist[kv.z >> 24], 1u);
            atomicAdd(&hist[kv.w >> 24], 1u);
        }
    }
    __syncthreads();

    #pragma unroll
    for (int pass = 0; pass < 4; pass++) {
        const int shift = 24 - pass*8;
        const unsigned int pref = s_pref;
        const unsigned int kk   = s_kk;
        if (t < 32) {
            const int base = t * 8;
            unsigned int vals[8];
            unsigned int s = 0;
            #pragma unroll
            for (int j = 0; j < 8; j++) { s += hist[base+j]; vals[j] = s; }
            unsigned int tot = s;
            #pragma unroll
            for (int off = 1; off < 32; off <<= 1) {
                unsigned int nb = __shfl_up_sync(0xffffffffu, tot, off);
                if (t >= off) tot += nb;
            }
            const unsigned int offset = tot - s;
            #pragma unroll
            for (int j = 0; j < 8; j++) hist[base+j] = vals[j] + offset;
        }
        __syncthreads();
        #pragma unroll
        for (int r = 0; r < 2; r++) {
            int bin = t + r*128;
            unsigned int cum  = hist[bin];
            unsigned int prev = bin ? hist[bin-1] : 0u;
            if (cum >= kk && prev < kk) {
                s_pref = pref | ((unsigned int)bin << shift);
                s_kk   = kk - prev;
            }
        }
        __syncthreads();
        if (pass < 3) {
            const unsigned int npref = s_pref;
            hist[t] = 0u; hist[t+128] = 0u;
            __syncthreads();
            const int nshift = shift - 8;
            const unsigned int nmask = 0xFFFFFFFFu << (nshift + 8);
            const uint4* keys4 = (const uint4*)keys;
            #pragma unroll
            for (int k = 0; k < 8; k++) {
                uint4 kv = keys4[k*128 + t];
                if ((kv.x & nmask) == npref) atomicAdd(&hist[(kv.x >> nshift) & 255u], 1u);
                if ((kv.y & nmask) == npref) atomicAdd(&hist[(kv.y >> nshift) & 255u], 1u);
                if ((kv.z & nmask) == npref) atomicAdd(&hist[(kv.z >> nshift) & 255u], 1u);
                if ((kv.w & nmask) == npref) atomicAdd(&hist[(kv.w >> nshift) & 255u], 1u);
            }
            __syncthreads();
        }
    }

    const unsigned int T = s_pref;
    {
        const uint4* keys4 = (const uint4*)keys;
        #pragma unroll
        for (int k = 0; k < 8; k++) {
            int q = k*128 + t;
            uint4 kv = keys4[q];
            unsigned int j0 = (unsigned)(q*4);
            #pragma unroll
            for (int m = 0; m < 4; m++) {
                unsigned int key = (m==0)?kv.x:(m==1)?kv.y:(m==2)?kv.z:kv.w;
                if (key < T) {
                    unsigned int pos = atomicAdd(&s_cnt, 1u);
                    if (pos < KNBR) sel[pos] = j0 + m;
                } else if (key == T) {
                    unsigned int tp = atomicAdd(&s_tcnt, 1u);
                    if (tp < 40u) ties[tp] = j0 + m;
                }
            }
        }
    }
    __syncthreads();

    if (t == 0) {
        unsigned int cnt = s_cnt, kk = s_kk, tc = s_tcnt;
        if (cnt > KNBR) cnt = KNBR;
        if (kk > KNBR - cnt) kk = KNBR - cnt;
        if (tc <= 40u) {
            for (unsigned int m = 0; m < kk; m++) {
                unsigned int best = 0xFFFFFFFFu, bi = m;
                for (unsigned int r = m; r < tc; r++)
                    if (ties[r] < best) { best = ties[r]; bi = r; }
                ties[bi] = ties[m]; ties[m] = best;
                sel[cnt + m] = best;
            }
        } else {
            unsigned int filled = 0;
            for (int j = 0; j < NPN && filled < kk; j++)
                if (keys[j] == T) { sel[cnt + filled] = (unsigned int)j; filled++; }
        }
    }
    __syncthreads();

    if (t < KNBR) {
        int j = (int)sel[t];
        float tx = tgt[j], ty = tgt[NPN+j], tz = tgt[2*NPN+j];
        float rx = tx - qx, ry = ty - qy, rz = tz - qz;
        float dist = sqrtf(rx*rx + ry*ry + rz*rz);
        float4* out4 = (float4*)g_feats;
        out4[(size_t)pq*SL + set*KNBR + t] = make_float4(rx, ry, rz, dist);
    }
}

// --------- layer-1 BN statistics (+ padded fp16 W2/W3 in block 0) ----------
__global__ __launch_bounds__(256) void stats1_kernel(const float* __restrict__ W1,
                                                     const float* __restrict__ b1,
                                                     const float* __restrict__ W2,
                                                     const float* __restrict__ W3) {
    __shared__ float w1s[C1*4];
    __shared__ float b1s[C1];
    __shared__ float ssum[C1], ssq[C1];
    const int t = threadIdx.x;

    if (blockIdx.x == 0) {
        for (int idx = t; idx < C2*C1; idx += 256) {
            int m = idx >> 6, k = idx & 63;
            g_W2Hp[m*WPAD + k] = __float2half_rn(W2[idx]);
        }
        for (int idx = t; idx < C3*C2; idx += 256) {
            int m = idx >> 6, k = idx & 63;
            g_W3Hp[m*WPAD + k] = __float2half_rn(W3[idx]);
        }
    }

    if (t < C1*4) w1s[t] = W1[t];
    if (t < C1)  { b1s[t] = b1[t]; ssum[t] = 0.f; ssq[t] = 0.f; }
    __syncthreads();

    const int c = t & 63, g = t >> 6;
    const int COLS_PER_BLOCK = NCOLS / 2048;
    const int col0 = blockIdx.x * COLS_PER_BLOCK;
    const float w0 = w1s[c*4+0], w1 = w1s[c*4+1], w2 = w1s[c*4+2], w3 = w1s[c*4+3];
    const float bc = b1s[c];
    float sum = 0.f, sq = 0.f;
    const float4* f4 = (const float4*)g_feats;
    for (int col = col0 + g; col < col0 + COLS_PER_BLOCK; col += 4) {
        float4 f = f4[col];
        float y = fmaf(w0, f.x, fmaf(w1, f.y, fmaf(w2, f.z, fmaf(w3, f.w, bc))));
        sum += y; sq = fmaf(y, y, sq);
    }
    atomicAdd(&ssum[c], sum);
    atomicAdd(&ssq[c],  sq);
    __syncthreads();
    if (t < C1) {
        atomicAdd(&g_s1[t], (double)ssum[t]);
        atomicAdd(&g_q1[t], (double)ssq[t]);
    }
}

// ---------------- layer2 via mma.sync (HMMA), 4 pts/block -------------------
// 8 warps; warp w: m-rows (w&3)*16 of point-pair (w>>2). A (W2) staged +
// frags loaded once; B (x2) computed from feats in fp32 then packed fp16.
__global__ __launch_bounds__(256) void layer2_kernel(const float* __restrict__ W1,
                                                     const float* __restrict__ b1,
                                                     const float* __restrict__ g1,
                                                     const float* __restrict__ be1,
                                                     const float* __restrict__ b2) {
    __shared__ __align__(16) __half Ah[C2*WPAD];         // 9216 B
    __shared__ __align__(16) __half Bh[PTS2][C1*WPAD];   // 4 x 9216 B
    __shared__ __align__(16) float fsh[PTS2*SL*4];       // 4096 B
    __shared__ float w1s[C1*4];
    __shared__ float b1s[C1], a1s[C1], d1s[C1];
    __shared__ float ssum[C2], ssq[C2];

    const int t    = threadIdx.x;
    const int wid  = t >> 5;
    const int lane = t & 31;
    const int p0   = blockIdx.x * PTS2;

    w1s[t] = W1[t];
    if (t < 64) {
        b1s[t] = b1[t]; ssum[t] = 0.f; ssq[t] = 0.f;
        const double cnt = (double)NCOLS;
        double m = g_s1[t] / cnt;
        double v = g_q1[t] / cnt - m*m;
        if (v < 0.0) v = 0.0;
        double a = (double)g1[t] / sqrt(v + 1e-3);
        a1s[t] = (float)a;
        d1s[t] = (float)((double)be1[t] - a*m);
    }
    ((float4*)fsh)[t] = ((const float4*)g_feats)[(size_t)p0*SL + t];

    {   // stage A: W2 fp16 padded (576 uint4)
        const uint4* src = (const uint4*)g_W2Hp;
        uint4* dst = (uint4*)Ah;
        for (int idx = t; idx < (C2*WPAD)/8; idx += 256)
            dst[idx] = __ldg(&src[idx]);
    }
    __syncthreads();

    {   // stage B: x2 = relu(bn1(W1 f + b1)) as half2 (2 slots/thread/iter)
        const float4* fsh4 = (const float4*)fsh;
        #pragma unroll
        for (int k = 0; k < 32; k++) {
            int idx = k*256 + t;              // 0..8191
            int pt = idx >> 11;
            int i  = (idx >> 5) & 63;
            int s2 = idx & 31;
            float wi0 = w1s[i*4+0], wi1 = w1s[i*4+1];
            float wi2 = w1s[i*4+2], wi3 = w1s[i*4+3];
            float bi = b1s[i], ai = a1s[i], di = d1s[i];
            float4 f0 = fsh4[pt*SL + 2*s2];
            float4 f1 = fsh4[pt*SL + 2*s2 + 1];
            float y0 = fmaf(wi0, f0.x, fmaf(wi1, f0.y, fmaf(wi2, f0.z, fmaf(wi3, f0.w, bi))));
            float y1 = fmaf(wi0, f1.x, fmaf(wi1, f1.y, fmaf(wi2, f1.z, fmaf(wi3, f1.w, bi))));
            float x0 = fmaxf(fmaf(ai, y0, di), 0.f);
            float x1 = fmaxf(fmaf(ai, y1, di), 0.f);
            *(__half2*)(&Bh[pt][i*WPAD + 2*s2]) = __floats2half2_rn(x0, x1);
        }
    }
    __syncthreads();

    // A fragments loaded once (warp covers m-rows (wid&3)*16)
    const int m0 = (wid & 3) * 16;
    const int pg = wid >> 2;              // point-pair group: 0 -> pts {0,1}, 1 -> {2,3}
    unsigned af[4][4];
    {
        int g = lane >> 3, r = lane & 7;
        int row  = m0 + (g & 1)*8 + r;
        int colb = (g >> 1)*8;
        #pragma unroll
        for (int ks = 0; ks < 4; ks++) {
            unsigned addr = smem_u32(Ah + row*WPAD + ks*16 + colb);
            asm volatile("ldmatrix.sync.aligned.m8n8.x4.shared.b16 {%0,%1,%2,%3}, [%4];"
                : "=r"(af[ks][0]), "=r"(af[ks][1]), "=r"(af[ks][2]), "=r"(af[ks][3])
                : "r"(addr));
        }
    }

    const int c_lo = m0 + (lane >> 2);
    const int c_hi = c_lo + 8;
    const float blo = b2[c_lo], bhi = b2[c_hi];
    float sum_lo = 0.f, sq_lo = 0.f, sum_hi = 0.f, sq_hi = 0.f;

    #pragma unroll
    for (int l = 0; l < 2; l++) {
        const int pt = pg*2 + l;
        float acc[8][4];
        #pragma unroll
        for (int nt = 0; nt < 8; nt++)
            #pragma unroll
            for (int j = 0; j < 4; j++) acc[nt][j] = 0.f;

        #pragma unroll
        for (int nt = 0; nt < 8; nt++) {
            #pragma unroll
            for (int ks = 0; ks < 4; ks++) {
                unsigned baddr = smem_u32(&Bh[pt][(ks*16 + (lane & 15))*WPAD + nt*8]);
                unsigned b0, b1r;
                asm volatile("ldmatrix.sync.aligned.m8n8.x2.trans.shared.b16 {%0,%1}, [%2];"
                    : "=r"(b0), "=r"(b1r) : "r"(baddr));
                asm volatile("mma.sync.aligned.m16n8k16.row.col.f32.f16.f16.f32 "
                    "{%0,%1,%2,%3},{%4,%5,%6,%7},{%8,%9},{%0,%1,%2,%3};"
                    : "+f"(acc[nt][0]), "+f"(acc[nt][1]), "+f"(acc[nt][2]), "+f"(acc[nt][3])
                    : "r"(af[ks][0]), "r"(af[ks][1]), "r"(af[ks][2]), "r"(af[ks][3]),
                      "r"(b0), "r"(b1r));
            }
        }

        __half* ybase = g_y2h + (size_t)(p0 + pt)*(C2*SL);
        #pragma unroll
        for (int nt = 0; nt < 8; nt++) {
            int s0 = nt*8 + (lane & 3)*2;
            float v0 = acc[nt][0] + blo, v1 = acc[nt][1] + blo;
            float v2 = acc[nt][2] + bhi, v3 = acc[nt][3] + bhi;
            sum_lo += v0 + v1; sq_lo = fmaf(v0, v0, fmaf(v1, v1, sq_lo));
            sum_hi += v2 + v3; sq_hi = fmaf(v2, v2, fmaf(v3, v3, sq_hi));
            __half2 hlo = __floats2half2_rn(v0, v1);
            __half2 hhi = __floats2half2_rn(v2, v3);
            *(__half2*)(ybase + c_lo*64 + s0) = hlo;
            *(__half2*)(ybase + c_hi*64 + s0) = hhi;
        }
    }

    atomicAdd(&ssum[c_lo], sum_lo); atomicAdd(&ssq[c_lo], sq_lo);
    atomicAdd(&ssum[c_hi], sum_hi); atomicAdd(&ssq[c_hi], sq_hi);
    __syncthreads();

    if (t < C2) {
        int r = blockIdx.x & (NSTRIPE-1);
        atomicAdd(&g_s2[r][t], (double)ssum[t]);
        atomicAdd(&g_q2[r][t], (double)ssq[t]);
    }
}

// ---------------- layer3 via mma.sync (HMMA), 4 pts/block -------------------
__global__ __launch_bounds__(256) void layer3_kernel(const float* __restrict__ b3,
                                                     const float* __restrict__ g2,
                                                     const float* __restrict__ be2) {
    __shared__ __align__(16) __half Asm[C3*WPAD];        // 18432 B
    __shared__ __align__(16) __half Bsm[PTS3][C2*WPAD];  // 4 x 9216 B
    __shared__ float a2s[C2], d2s[C2];
    __shared__ float ssum[C3], ssq[C3];

    const int t    = threadIdx.x;
    const int wid  = t >> 5;
    const int lane = t & 31;
    const int p0   = blockIdx.x * PTS3;

    {   // parallel BN2 finalize (reduction buffers aliased into Asm)
        double* red_s = (double*)Asm;
        double* red_q = ((double*)Asm) + 256;
        const int ch = t & 63, grp = t >> 6;
        double s = 0.0, q = 0.0;
        #pragma unroll
        for (int r = 0; r < 8; r++) {
            s += g_s2[grp*8 + r][ch];
            q += g_q2[grp*8 + r][ch];
        }
        red_s[t] = s; red_q[t] = q;
        __syncthreads();
        if (t < 64) {
            double ss = (red_s[t] + red_s[t+64]) + (red_s[t+128] + red_s[t+192]);
            double qq = (red_q[t] + red_q[t+64]) + (red_q[t+128] + red_q[t+192]);
            const double cnt = (double)NCOLS;
            double m = ss / cnt;
            double v = qq / cnt - m*m;
            if (v < 0.0) v = 0.0;
            double a = (double)g2[t] / sqrt(v + 1e-3);
            a2s[t] = (float)a;
            d2s[t] = (float)((double)be2[t] - a*m);
        }
        if (t < 128) { ssum[t] = 0.f; ssq[t] = 0.f; }
        __syncthreads();
    }

    {   // stage A: 1152 uint4 from padded fp16 W3
        const uint4* src = (const uint4*)g_W3Hp;
        uint4* dst = (uint4*)Asm;
        for (int idx = t; idx < (C3*WPAD)/8; idx += 256)
            dst[idx] = __ldg(&src[idx]);
    }
    {   // stage B for all PTS3 points
        const uint4* y2p = (const uint4*)(g_y2h + (size_t)p0*(C2*SL));
        #pragma unroll
        for (int k = 0; k < 2*PTS3; k++) {
            int idx = k*256 + t;
            int pt = idx >> 9;
            int w  = idx & 511;
            int i  = w >> 3;
            int ch = w & 7;
            float a = a2s[i], d = d2s[i];
            uint4 pk = __ldg(&y2p[idx]);
            float2 f0 = __half22float2(*(__half2*)&pk.x);
            float2 f1 = __half22float2(*(__half2*)&pk.y);
            float2 f2 = __half22float2(*(__half2*)&pk.z);
            float2 f3 = __half22float2(*(__half2*)&pk.w);
            __half2 h0 = __floats2half2_rn(fmaxf(fmaf(a, f0.x, d), 0.f),
                                           fmaxf(fmaf(a, f0.y, d), 0.f));
            __half2 h1 = __floats2half2_rn(fmaxf(fmaf(a, f1.x, d), 0.f),
                                           fmaxf(fmaf(a, f1.y, d), 0.f));
            __half2 h2 = __floats2half2_rn(fmaxf(fmaf(a, f2.x, d), 0.f),
                                           fmaxf(fmaf(a, f2.y, d), 0.f));
            __half2 h3 = __floats2half2_rn(fmaxf(fmaf(a, f3.x, d), 0.f),
                                           fmaxf(fmaf(a, f3.y, d), 0.f));
            uint4 o;
            o.x = *(unsigned int*)&h0; o.y = *(unsigned int*)&h1;
            o.z = *(unsigned int*)&h2; o.w = *(unsigned int*)&h3;
            *(uint4*)(&Bsm[pt][i*WPAD + ch*8]) = o;
        }
    }
    __syncthreads();

    const int m0 = wid * 16;
    unsigned af[4][4];
    {
        int g = lane >> 3, r = lane & 7;
        int row  = m0 + (g & 1)*8 + r;
        int colb = (g >> 1)*8;
        #pragma unroll
        for (int ks = 0; ks < 4; ks++) {
            unsigned addr = smem_u32(Asm + row*WPAD + ks*16 + colb);
            asm volatile("ldmatrix.sync.aligned.m8n8.x4.shared.b16 {%0,%1,%2,%3}, [%4];"
                : "=r"(af[ks][0]), "=r"(af[ks][1]), "=r"(af[ks][2]), "=r"(af[ks][3])
                : "r"(addr));
        }
    }

    const int c_lo = m0 + (lane >> 2);
    const int c_hi = c_lo + 8;
    const float blo = b3[c_lo], bhi = b3[c_hi];
    float sum_lo = 0.f, sq_lo = 0.f, sum_hi = 0.f, sq_hi = 0.f;

    #pragma unroll
    for (int pt = 0; pt < PTS3; pt++) {
        float acc[8][4];
        #pragma unroll
        for (int nt = 0; nt < 8; nt++)
            #pragma unroll
            for (int j = 0; j < 4; j++) acc[nt][j] = 0.f;

        #pragma unroll
        for (int nt = 0; nt < 8; nt++) {
            #pragma unroll
            for (int ks = 0; ks < 4; ks++) {
                unsigned baddr = smem_u32(&Bsm[pt][(ks*16 + (lane & 15))*WPAD + nt*8]);
                unsigned b0, b1;
                asm volatile("ldmatrix.sync.aligned.m8n8.x2.trans.shared.b16 {%0,%1}, [%2];"
                    : "=r"(b0), "=r"(b1) : "r"(baddr));
                asm volatile("mma.sync.aligned.m16n8k16.row.col.f32.f16.f16.f32 "
                    "{%0,%1,%2,%3},{%4,%5,%6,%7},{%8,%9},{%0,%1,%2,%3};"
                    : "+f"(acc[nt][0]), "+f"(acc[nt][1]), "+f"(acc[nt][2]), "+f"(acc[nt][3])
                    : "r"(af[ks][0]), "r"(af[ks][1]), "r"(af[ks][2]), "r"(af[ks][3]),
                      "r"(b0), "r"(b1));
            }
        }

        __half* ybase = g_y3h + (size_t)(p0 + pt)*(C3*SL);
        #pragma unroll
        for (int nt = 0; nt < 8; nt++) {
            int s0 = nt*8 + (lane & 3)*2;
            float v0 = acc[nt][0] + blo, v1 = acc[nt][1] + blo;
            float v2 = acc[nt][2] + bhi, v3 = acc[nt][3] + bhi;
            sum_lo += v0 + v1; sq_lo = fmaf(v0, v0, fmaf(v1, v1, sq_lo));
            sum_hi += v2 + v3; sq_hi = fmaf(v2, v2, fmaf(v3, v3, sq_hi));
            __half2 hlo = __floats2half2_rn(v0, v1);
            __half2 hhi = __floats2half2_rn(v2, v3);
            *(__half2*)(ybase + c_lo*64 + s0) = hlo;
            *(__half2*)(ybase + c_hi*64 + s0) = hhi;
        }
    }

    atomicAdd(&ssum[c_lo], sum_lo); atomicAdd(&ssq[c_lo], sq_lo);
    atomicAdd(&ssum[c_hi], sum_hi); atomicAdd(&ssq[c_hi], sq_hi);
    __syncthreads();

    if (t < C3) {
        int r = blockIdx.x & (NSTRIPE-1);
        atomicAdd(&g_s3[r][t], (double)ssum[t]);
        atomicAdd(&g_q3[r][t], (double)ssq[t]);
    }
}

__global__ void fin3_kernel(const float* __restrict__ g3, const float* __restrict__ be3) {
    int c = threadIdx.x;   // 128
    double s = 0.0, q = 0.0;
    for (int r = 0; r < NSTRIPE; r++) { s += g_s3[r][c]; q += g_q3[r][c]; }
    const double cnt = (double)NCOLS;
    double m = s / cnt;
    double v = q / cnt - m*m;
    if (v < 0.0) v = 0.0;
    double a = (double)g3[c] / sqrt(v + 1e-3);
    g_a3[c] = (float)a;
    g_d3[c] = (float)((double)be3[c] - a*m);
}

// --------------------------- max over channels, softmax over slots, fuse ---
__global__ __launch_bounds__(256) void fuse_kernel(const float* __restrict__ p1,
                                                   float* __restrict__ out) {
    __shared__ float pm[8][SL];
    __shared__ float sc[SL];
    __shared__ float ex[SL];
    __shared__ float rx[SL], ry[SL], rz[SL];

    const int t = threadIdx.x;
    const int p = blockIdx.x;
    const int s2 = t & 31, cg = t >> 5;

    const __half2* y3h2 = (const __half2*)(g_y3h + (size_t)p*(C3*SL));
    float m0 = -INFINITY, m1 = -INFINITY;
    #pragma unroll 4
    for (int ci = 0; ci < 16; ci++) {
        int c = cg*16 + ci;
        float a = g_a3[c], d = g_d3[c];
        float2 f = __half22float2(y3h2[c*32 + s2]);
        m0 = fmaxf(m0, fmaf(a, f.x, d));
        m1 = fmaxf(m1, fmaf(a, f.y, d));
    }
    pm[cg][2*s2]   = m0;
    pm[cg][2*s2+1] = m1;
    __syncthreads();

    if (t < SL) {
        float mm = pm[0][t];
        #pragma unroll
        for (int g = 1; g < 8; g++) mm = fmaxf(mm, pm[g][t]);
        sc[t] = fmaxf(mm, 0.f);
    }
    __syncthreads();

    if (t < SL) {
        float mx = sc[0];
        #pragma unroll 8
        for (int i = 1; i < SL; i++) mx = fmaxf(mx, sc[i]);
        ex[t] = expf(sc[t] - mx);
    }
    __syncthreads();

    if (t < SL) {
        float ssum = 0.f;
        #pragma unroll 8
        for (int i = 0; i < SL; i++) ssum += ex[i];
        float w = ex[t] / ssum;
        float4 f = ((const float4*)g_feats)[(size_t)p*SL + t];
        rx[t] = w*f.x; ry[t] = w*f.y; rz[t] = w*f.z;
    }
    __syncthreads();

    for (int off = 32; off >= 1; off >>= 1) {
        if (t < off) { rx[t] += rx[t+off]; ry[t] += ry[t+off]; rz[t] += rz[t+off]; }
        __syncthreads();
    }

    if (t == 0) {
        const int b = p >> 12, n = p & (NPN-1);
        const float* q = p1 + (size_t)b*3*NPN;
        out[(size_t)b*3*NPN + n]          = q[n]        + rx[0];
        out[(size_t)b*3*NPN + NPN + n]    = q[NPN+n]    + ry[0];
        out[(size_t)b*3*NPN + 2*NPN + n]  = q[2*NPN+n]  + rz[0];
    }
}

// --------------------------------------------------------------------------
extern "C" void kernel_launch(void* const* d_in, const int* in_sizes, int n_in,
                              void* d_out, int out_size) {
    const float* points1 = (const float*)d_in[0];
    const float* points2 = (const float*)d_in[1];
    const float* W1  = (const float*)d_in[4];
    const float* b1  = (const float*)d_in[5];
    const float* g1  = (const float*)d_in[6];
    const float* be1 = (const float*)d_in[7];
    const float* W2  = (const float*)d_in[8];
    const float* b2  = (const float*)d_in[9];
    const float* g2  = (const float*)d_in[10];
    const float* be2 = (const float*)d_in[11];
    const float* W3  = (const float*)d_in[12];
    const float* b3  = (const float*)d_in[13];
    const float* g3  = (const float*)d_in[14];
    const float* be3 = (const float*)d_in[15];
    float* out = (float*)d_out;

    knn_kernel<<<BB*NPN*2, 128>>>(points1, points2);                 // 1
    stats1_kernel<<<2048, 256>>>(W1, b1, W2, W3);                    // 2
    layer2_kernel<<<NPTS/PTS2, 256>>>(W1, b1, g1, be1, b2);          // 3
    layer3_kernel<<<NPTS/PTS3, 256>>>(b3, g2, be2);                  // 4 -> ncu
    fin3_kernel<<<1, C3>>>(g3, be3);                                 // 5
    fuse_kernel<<<NPTS, 256>>>(points1, out);                        // 6
}